// round 9
// baseline (speedup 1.0000x reference)
#include <cuda_runtime.h>
#include <cuda_bf16.h>

#define NN 100000
#define NE_MAX 1600000
#define INC 64
#define HIDC 128
#define OUTC 64
#define NCLS 20
#define NCHUNK 98          // ceil(NN/1024)

// ---------------- device scratch (static globals; no allocation) ------------
__device__ int   g_is64;
__device__ __align__(16) int2 g_edges[NE_MAX];
__device__ int   g_degi[NN];
__device__ int   g_rowstart[NN];
__device__ int   g_cursor[NN];
__device__ int   g_srclist[NE_MAX];
__device__ int   g_chunksum[NCHUNK];
__device__ int   g_chunkoff[NCHUNK];
__device__ float g_dinv[NN];
__device__ __align__(16) float g_agg1[(size_t)NN * INC];
__device__ __align__(16) float g_h1[(size_t)NN * HIDC];
__device__ __align__(16) float g_p[(size_t)NN * OUTC];
__device__ __align__(16) float g_s2[(size_t)NN * OUTC];
__device__ __align__(16) float g_h2[(size_t)NN * OUTC];

// ---------------- CSR build kernels -----------------------------------------

__global__ void k_detect(const int* __restrict__ ei32, int n32, int* __restrict__ flag) {
    __shared__ int s_any;
    if (threadIdx.x == 0) s_any = 0;
    __syncthreads();
    int nonzero = 0;
    int limit = n32 < 16384 ? n32 : 16384;
    for (int i = 1 + 2 * threadIdx.x; i < limit; i += 2 * blockDim.x)
        if (ei32[i] != 0) nonzero = 1;
    if (nonzero) atomicOr(&s_any, 1);
    __syncthreads();
    if (threadIdx.x == 0) *flag = (s_any == 0) ? 1 : 0;  // all-zero odd words -> int64
}

__global__ void k_zero_deg(int* __restrict__ degi) {
    int i = blockIdx.x * blockDim.x + threadIdx.x;
    if (i < NN) degi[i] = 0;
}

__global__ void k_convert(const void* __restrict__ ei, int nE, int2* __restrict__ edges,
                          int* __restrict__ degi, const int* __restrict__ flag) {
    int e = blockIdx.x * blockDim.x + threadIdx.x;
    if (e >= nE) return;
    int s, d;
    if (*flag) {
        s = (int)((const long long*)ei)[e];
        d = (int)((const long long*)ei)[(long long)nE + e];
    } else {
        s = ((const int*)ei)[e];
        d = ((const int*)ei)[nE + e];
    }
    if ((unsigned)s >= NN) s = 0;
    if ((unsigned)d >= NN) d = 0;
    edges[e] = make_int2(s, d);
    atomicAdd(&degi[d], 1);
}

__global__ __launch_bounds__(1024) void k_scanA(const int* __restrict__ degi,
                                                int* __restrict__ chunksum) {
    __shared__ int s[1024];
    int i = blockIdx.x * 1024 + threadIdx.x;
    s[threadIdx.x] = (i < NN) ? degi[i] : 0;
    __syncthreads();
    for (int off = 512; off > 0; off >>= 1) {
        if (threadIdx.x < off) s[threadIdx.x] += s[threadIdx.x + off];
        __syncthreads();
    }
    if (threadIdx.x == 0) chunksum[blockIdx.x] = s[0];
}

__global__ void k_scanB(const int* __restrict__ chunksum, int* __restrict__ chunkoff) {
    __shared__ int s[128];
    int v = (threadIdx.x < NCHUNK) ? chunksum[threadIdx.x] : 0;
    s[threadIdx.x] = v;
    __syncthreads();
    for (int off = 1; off < 128; off <<= 1) {
        int t = (threadIdx.x >= off) ? s[threadIdx.x - off] : 0;
        __syncthreads();
        s[threadIdx.x] += t;
        __syncthreads();
    }
    if (threadIdx.x < NCHUNK) chunkoff[threadIdx.x] = s[threadIdx.x] - v;
}

__global__ __launch_bounds__(1024) void k_scanC(const int* __restrict__ degi,
                                                const int* __restrict__ chunkoff,
                                                int* __restrict__ rowstart,
                                                int* __restrict__ cursor,
                                                float* __restrict__ dinv) {
    __shared__ int s[1024];
    int i = blockIdx.x * 1024 + threadIdx.x;
    int v = (i < NN) ? degi[i] : 0;
    s[threadIdx.x] = v;
    __syncthreads();
    for (int off = 1; off < 1024; off <<= 1) {
        int t = (threadIdx.x >= off) ? s[threadIdx.x - off] : 0;
        __syncthreads();
        s[threadIdx.x] += t;
        __syncthreads();
    }
    if (i < NN) {
        int excl = s[threadIdx.x] - v + chunkoff[blockIdx.x];
        rowstart[i] = excl;
        cursor[i] = excl;
        dinv[i] = 1.0f / fmaxf((float)v, 1.0f);
    }
}

__global__ void k_scatter(const int2* __restrict__ edges, int nE,
                          int* __restrict__ cursor, int* __restrict__ srclist) {
    int e = blockIdx.x * blockDim.x + threadIdx.x;
    if (e >= nE) return;
    int2 ed = edges[e];
    int p = atomicAdd(&cursor[ed.y], 1);
    srclist[p] = ed.x;
}

// ---------------- gather kernels ---------------------------------------------

__global__ __launch_bounds__(256) void k_gather1(
    const float4* __restrict__ feat, const int* __restrict__ rowstart,
    const int* __restrict__ degi, const int* __restrict__ srclist,
    const float* __restrict__ dinv, float4* __restrict__ out) {
    int node = blockIdx.x * 8 + (threadIdx.x >> 5);
    if (node >= NN) return;
    int lane = threadIdx.x & 31;
    int half = lane >> 4;
    int c = lane & 15;
    int beg = rowstart[node];
    int cnt = degi[node];
    float4 acc = make_float4(0.f, 0.f, 0.f, 0.f);
    for (int i = half; i < cnt; i += 2) {
        int s = __ldg(&srclist[beg + i]);
        float4 v = __ldg(&feat[(long long)s * 16 + c]);
        acc.x += v.x; acc.y += v.y; acc.z += v.z; acc.w += v.w;
    }
    acc.x += __shfl_xor_sync(0xffffffffu, acc.x, 16);
    acc.y += __shfl_xor_sync(0xffffffffu, acc.y, 16);
    acc.z += __shfl_xor_sync(0xffffffffu, acc.z, 16);
    acc.w += __shfl_xor_sync(0xffffffffu, acc.w, 16);
    if (half == 0) {
        float di = dinv[node];
        out[(long long)node * 16 + c] =
            make_float4(acc.x * di, acc.y * di, acc.z * di, acc.w * di);
    }
}

__global__ __launch_bounds__(256) void k_gather2(
    const float4* __restrict__ pfeat, const int* __restrict__ rowstart,
    const int* __restrict__ degi, const int* __restrict__ srclist,
    const float* __restrict__ dinv, const float4* __restrict__ s2,
    const float4* __restrict__ b2, float4* __restrict__ h2) {
    int node = blockIdx.x * 8 + (threadIdx.x >> 5);
    if (node >= NN) return;
    int lane = threadIdx.x & 31;
    int half = lane >> 4;
    int c = lane & 15;
    int beg = rowstart[node];
    int cnt = degi[node];
    float4 acc = make_float4(0.f, 0.f, 0.f, 0.f);
    for (int i = half; i < cnt; i += 2) {
        int s = __ldg(&srclist[beg + i]);
        float4 v = __ldg(&pfeat[(long long)s * 16 + c]);
        acc.x += v.x; acc.y += v.y; acc.z += v.z; acc.w += v.w;
    }
    acc.x += __shfl_xor_sync(0xffffffffu, acc.x, 16);
    acc.y += __shfl_xor_sync(0xffffffffu, acc.y, 16);
    acc.z += __shfl_xor_sync(0xffffffffu, acc.z, 16);
    acc.w += __shfl_xor_sync(0xffffffffu, acc.w, 16);
    if (half == 0) {
        float di = dinv[node];
        float4 sv = __ldg(&s2[(long long)node * 16 + c]);
        float4 bv = __ldg(&b2[c]);
        float4 r;
        r.x = fmaxf(sv.x + acc.x * di + bv.x, 0.f);
        r.y = fmaxf(sv.y + acc.y * di + bv.y, 0.f);
        r.z = fmaxf(sv.z + acc.z * di + bv.z, 0.f);
        r.w = fmaxf(sv.w + acc.w * di + bv.w, 0.f);
        h2[(long long)node * 16 + c] = r;
    }
}

// ---------------- GEMM kernels (2D register tiling, 64 nodes/block) ----------

// layer1: h1 = relu(x@Ws + agg@Wn + b). 64 nodes/block, 256 threads.
// Thread tile: 4 cols (j0 = lane*4) x 8 nodes (warp -> node group).
__global__ __launch_bounds__(256) void k_layer1(
    const float* __restrict__ x, const float* __restrict__ agg,
    const float* __restrict__ Wself, const float* __restrict__ Wneigh,
    const float* __restrict__ b, float* __restrict__ h1) {
    __shared__ float sW[INC * HIDC];   // 32 KB: [k][j] 64x128
    __shared__ float sF[64 * INC];     // 16 KB: [n][k] 64x64
    const int tid = threadIdx.x;
    const int lane = tid & 31;
    const int wrp = tid >> 5;          // 0..7
    const int j0 = lane * 4;
    const int nb = wrp * 8;
    const int n0 = blockIdx.x * 64;

    float4 acc[8];
#pragma unroll
    for (int n = 0; n < 8; n++) acc[n] = make_float4(0.f, 0.f, 0.f, 0.f);

#pragma unroll
    for (int pass = 0; pass < 2; pass++) {
        const float* W = pass ? Wneigh : Wself;
        const float* F = pass ? agg : x;
        if (pass) __syncthreads();
        for (int i = tid; i < INC * HIDC / 4; i += 256)
            ((float4*)sW)[i] = ((const float4*)W)[i];
        for (int i = tid; i < 64 * INC / 4; i += 256) {
            int row = i >> 4;                       // 16 float4 per node row
            int rglob = n0 + row; if (rglob >= NN) rglob = NN - 1;
            ((float4*)sF)[i] = ((const float4*)F)[(long long)rglob * 16 + (i & 15)];
        }
        __syncthreads();
#pragma unroll 4
        for (int k4 = 0; k4 < 16; k4++) {
            float4 w0 = *(const float4*)&sW[(k4 * 4 + 0) * HIDC + j0];
            float4 w1 = *(const float4*)&sW[(k4 * 4 + 1) * HIDC + j0];
            float4 w2 = *(const float4*)&sW[(k4 * 4 + 2) * HIDC + j0];
            float4 w3 = *(const float4*)&sW[(k4 * 4 + 3) * HIDC + j0];
#pragma unroll
            for (int n = 0; n < 8; n++) {
                float4 f = *(const float4*)&sF[(nb + n) * INC + k4 * 4];
                acc[n].x = fmaf(f.x, w0.x, acc[n].x);
                acc[n].y = fmaf(f.x, w0.y, acc[n].y);
                acc[n].z = fmaf(f.x, w0.z, acc[n].z);
                acc[n].w = fmaf(f.x, w0.w, acc[n].w);
                acc[n].x = fmaf(f.y, w1.x, acc[n].x);
                acc[n].y = fmaf(f.y, w1.y, acc[n].y);
                acc[n].z = fmaf(f.y, w1.z, acc[n].z);
                acc[n].w = fmaf(f.y, w1.w, acc[n].w);
                acc[n].x = fmaf(f.z, w2.x, acc[n].x);
                acc[n].y = fmaf(f.z, w2.y, acc[n].y);
                acc[n].z = fmaf(f.z, w2.z, acc[n].z);
                acc[n].w = fmaf(f.z, w2.w, acc[n].w);
                acc[n].x = fmaf(f.w, w3.x, acc[n].x);
                acc[n].y = fmaf(f.w, w3.y, acc[n].y);
                acc[n].z = fmaf(f.w, w3.z, acc[n].z);
                acc[n].w = fmaf(f.w, w3.w, acc[n].w);
            }
        }
    }
    float4 bv = *(const float4*)&b[j0];
#pragma unroll
    for (int n = 0; n < 8; n++) {
        int rglob = n0 + nb + n;
        if (rglob < NN) {
            float4 r;
            r.x = fmaxf(acc[n].x + bv.x, 0.f);
            r.y = fmaxf(acc[n].y + bv.y, 0.f);
            r.z = fmaxf(acc[n].z + bv.z, 0.f);
            r.w = fmaxf(acc[n].w + bv.w, 0.f);
            *(float4*)&h1[(long long)rglob * HIDC + j0] = r;
        }
    }
}

// dual GEMM: s2 = h1@Ws2, p = h1@Wn2. 128 virtual cols = [S 0..63 | P 64..127].
// K=128 in two 64-k passes. 64 nodes/block, 256 threads, 4 cols x 8 nodes tile.
__global__ __launch_bounds__(256) void k_dual(
    const float* __restrict__ h1,
    const float* __restrict__ Wself2, const float* __restrict__ Wneigh2,
    float* __restrict__ s2, float* __restrict__ p) {
    __shared__ float sW[64 * 128];     // 32 KB: [kk][jv] for current k-slice
    __shared__ float sF[64 * 64];      // 16 KB: [n][kk]
    const int tid = threadIdx.x;
    const int lane = tid & 31;
    const int wrp = tid >> 5;
    const int j0 = lane * 4;           // virtual col (all 4 in same matrix)
    const int nb = wrp * 8;
    const int n0 = blockIdx.x * 64;

    float4 acc[8];
#pragma unroll
    for (int n = 0; n < 8; n++) acc[n] = make_float4(0.f, 0.f, 0.f, 0.f);

#pragma unroll
    for (int kp = 0; kp < 2; kp++) {
        if (kp) __syncthreads();
        for (int i = tid * 4; i < 64 * 128; i += 256 * 4) {
            int kk = i >> 7, jv = i & 127;
            const float* W = (jv < 64) ? Wself2 : Wneigh2;
            *(float4*)&sW[i] = *(const float4*)&W[(kp * 64 + kk) * OUTC + (jv & 63)];
        }
        for (int i = tid * 4; i < 64 * 64; i += 256 * 4) {
            int n = i >> 6, kk = i & 63;
            int rglob = n0 + n; if (rglob >= NN) rglob = NN - 1;
            *(float4*)&sF[i] = *(const float4*)&h1[(long long)rglob * HIDC + kp * 64 + kk];
        }
        __syncthreads();
#pragma unroll 4
        for (int k4 = 0; k4 < 16; k4++) {
            float4 w0 = *(const float4*)&sW[(k4 * 4 + 0) * 128 + j0];
            float4 w1 = *(const float4*)&sW[(k4 * 4 + 1) * 128 + j0];
            float4 w2 = *(const float4*)&sW[(k4 * 4 + 2) * 128 + j0];
            float4 w3 = *(const float4*)&sW[(k4 * 4 + 3) * 128 + j0];
#pragma unroll
            for (int n = 0; n < 8; n++) {
                float4 f = *(const float4*)&sF[(nb + n) * 64 + k4 * 4];
                acc[n].x = fmaf(f.x, w0.x, acc[n].x);
                acc[n].y = fmaf(f.x, w0.y, acc[n].y);
                acc[n].z = fmaf(f.x, w0.z, acc[n].z);
                acc[n].w = fmaf(f.x, w0.w, acc[n].w);
                acc[n].x = fmaf(f.y, w1.x, acc[n].x);
                acc[n].y = fmaf(f.y, w1.y, acc[n].y);
                acc[n].z = fmaf(f.y, w1.z, acc[n].z);
                acc[n].w = fmaf(f.y, w1.w, acc[n].w);
                acc[n].x = fmaf(f.z, w2.x, acc[n].x);
                acc[n].y = fmaf(f.z, w2.y, acc[n].y);
                acc[n].z = fmaf(f.z, w2.z, acc[n].z);
                acc[n].w = fmaf(f.z, w2.w, acc[n].w);
                acc[n].x = fmaf(f.w, w3.x, acc[n].x);
                acc[n].y = fmaf(f.w, w3.y, acc[n].y);
                acc[n].z = fmaf(f.w, w3.z, acc[n].z);
                acc[n].w = fmaf(f.w, w3.w, acc[n].w);
            }
        }
    }
    float* dst = (j0 < 64) ? s2 : p;
    int jd = j0 & 63;
#pragma unroll
    for (int n = 0; n < 8; n++) {
        int rglob = n0 + nb + n;
        if (rglob < NN)
            *(float4*)&dst[(long long)rglob * OUTC + jd] = acc[n];
    }
}

// classifier: out = h2 @ wc + bc
__global__ __launch_bounds__(256) void k_out(const float* __restrict__ h2,
                                             const float* __restrict__ wc,
                                             const float* __restrict__ bc,
                                             float* __restrict__ out) {
    __shared__ float sW[OUTC * NCLS];
    __shared__ float sB[NCLS];
    __shared__ float sH[12 * 65];
    const int tid = threadIdx.x;
    const int n0 = blockIdx.x * 12;
    const int nmax = min(12, NN - n0);
    for (int i = tid; i < OUTC * NCLS; i += 256) sW[i] = wc[i];
    if (tid < NCLS) sB[tid] = bc[tid];
    for (int i = tid; i < nmax * OUTC; i += 256) {
        int ln = i >> 6, k = i & 63;
        sH[ln * 65 + k] = h2[(long long)(n0 + ln) * OUTC + k];
    }
    __syncthreads();
    if (tid < 240) {
        int ln = tid / 20, c = tid % 20;
        if (ln < nmax) {
            float acc = sB[c];
#pragma unroll
            for (int k = 0; k < OUTC; k++)
                acc = fmaf(sH[ln * 65 + k], sW[k * NCLS + c], acc);
            out[(long long)(n0 + ln) * NCLS + c] = acc;
        }
    }
}

// ---------------- launch ----------------------------------------------------
extern "C" void kernel_launch(void* const* d_in, const int* in_sizes, int n_in,
                              void* d_out, int out_size) {
    const float* x   = (const float*)d_in[0];
    const void*  ei  = d_in[1];
    const float* ws1 = (const float*)d_in[2];
    const float* wn1 = (const float*)d_in[3];
    const float* b1  = (const float*)d_in[4];
    const float* ws2 = (const float*)d_in[5];
    const float* wn2 = (const float*)d_in[6];
    const float* b2  = (const float*)d_in[7];
    const float* wc  = (const float*)d_in[8];
    const float* bc  = (const float*)d_in[9];
    float* out = (float*)d_out;

    int nE = in_sizes[1] / 2;
    if (nE > NE_MAX) nE = NE_MAX;

    void *p_flag, *p_edges, *p_degi, *p_rs, *p_cur, *p_src, *p_cs, *p_co;
    void *p_dinv, *p_agg1, *p_h1, *p_pp, *p_s2, *p_h2;
    cudaGetSymbolAddress(&p_flag, g_is64);
    cudaGetSymbolAddress(&p_edges, g_edges);
    cudaGetSymbolAddress(&p_degi, g_degi);
    cudaGetSymbolAddress(&p_rs,   g_rowstart);
    cudaGetSymbolAddress(&p_cur,  g_cursor);
    cudaGetSymbolAddress(&p_src,  g_srclist);
    cudaGetSymbolAddress(&p_cs,   g_chunksum);
    cudaGetSymbolAddress(&p_co,   g_chunkoff);
    cudaGetSymbolAddress(&p_dinv, g_dinv);
    cudaGetSymbolAddress(&p_agg1, g_agg1);
    cudaGetSymbolAddress(&p_h1,   g_h1);
    cudaGetSymbolAddress(&p_pp,   g_p);
    cudaGetSymbolAddress(&p_s2,   g_s2);
    cudaGetSymbolAddress(&p_h2,   g_h2);
    int*   flag  = (int*)p_flag;
    int2*  edges = (int2*)p_edges;
    int*   degi  = (int*)p_degi;
    int*   rs    = (int*)p_rs;
    int*   cur   = (int*)p_cur;
    int*   src   = (int*)p_src;
    int*   cs    = (int*)p_cs;
    int*   co    = (int*)p_co;
    float* dinv  = (float*)p_dinv;
    float* agg1  = (float*)p_agg1;
    float* h1    = (float*)p_h1;
    float* pp    = (float*)p_pp;
    float* s2    = (float*)p_s2;
    float* h2    = (float*)p_h2;

    // dtype detect + CSR build
    k_detect<<<1, 256>>>((const int*)ei, in_sizes[1], flag);
    k_zero_deg<<<(NN + 255) / 256, 256>>>(degi);
    k_convert<<<(nE + 255) / 256, 256>>>(ei, nE, edges, degi, flag);
    k_scanA<<<NCHUNK, 1024>>>(degi, cs);
    k_scanB<<<1, 128>>>(cs, co);
    k_scanC<<<NCHUNK, 1024>>>(degi, co, rs, cur, dinv);
    k_scatter<<<(nE + 255) / 256, 256>>>(edges, nE, cur, src);

    // layer 1
    k_gather1<<<(NN + 7) / 8, 256>>>((const float4*)x, rs, degi, src, dinv,
                                     (float4*)agg1);
    k_layer1<<<(NN + 63) / 64, 256>>>(x, agg1, ws1, wn1, b1, h1);

    // layer 2
    k_dual<<<(NN + 63) / 64, 256>>>(h1, ws2, wn2, s2, pp);
    k_gather2<<<(NN + 7) / 8, 256>>>((const float4*)pp, rs, degi, src, dinv,
                                     (const float4*)s2, (const float4*)b2,
                                     (float4*)h2);

    // classifier
    k_out<<<(NN + 11) / 12, 256>>>(h2, wc, bc, out);
}

// round 10
// speedup vs baseline: 1.7532x; 1.7532x over previous
#include <cuda_runtime.h>
#include <cuda_bf16.h>

#define NN 100000
#define NE_MAX 1600000
#define INC 64
#define HIDC 128
#define OUTC 64
#define NCLS 20
#define NCHUNK 98          // ceil(NN/1024)

// ---------------- device scratch (static globals; no allocation) ------------
__device__ int   g_is64;
__device__ __align__(16) int2 g_edges[NE_MAX];
__device__ int   g_degi[NN];
__device__ int   g_rowstart[NN];
__device__ int   g_cursor[NN];
__device__ int   g_srclist[NE_MAX];
__device__ int   g_chunksum[NCHUNK];
__device__ int   g_chunkoff[NCHUNK];
__device__ float g_dinv[NN];
__device__ __align__(16) float g_agg1[(size_t)NN * INC];
__device__ __align__(16) float g_h1[(size_t)NN * HIDC];
__device__ __align__(16) float g_p[(size_t)NN * OUTC];
__device__ __align__(16) float g_s2[(size_t)NN * OUTC];
__device__ __align__(16) float g_h2[(size_t)NN * OUTC];

// ---------------- CSR build kernels -----------------------------------------

__global__ void k_detect(const int* __restrict__ ei32, int n32, int* __restrict__ flag) {
    __shared__ int s_any;
    if (threadIdx.x == 0) s_any = 0;
    __syncthreads();
    int nonzero = 0;
    int limit = n32 < 16384 ? n32 : 16384;
    for (int i = 1 + 2 * threadIdx.x; i < limit; i += 2 * blockDim.x)
        if (ei32[i] != 0) nonzero = 1;
    if (nonzero) atomicOr(&s_any, 1);
    __syncthreads();
    if (threadIdx.x == 0) *flag = (s_any == 0) ? 1 : 0;  // all-zero odd words -> int64
}

__global__ void k_zero_deg(int* __restrict__ degi) {
    int i = blockIdx.x * blockDim.x + threadIdx.x;
    if (i < NN) degi[i] = 0;
}

__global__ void k_convert(const void* __restrict__ ei, int nE, int2* __restrict__ edges,
                          int* __restrict__ degi, const int* __restrict__ flag) {
    int e = blockIdx.x * blockDim.x + threadIdx.x;
    if (e >= nE) return;
    int s, d;
    if (*flag) {
        s = (int)((const long long*)ei)[e];
        d = (int)((const long long*)ei)[(long long)nE + e];
    } else {
        s = ((const int*)ei)[e];
        d = ((const int*)ei)[nE + e];
    }
    if ((unsigned)s >= NN) s = 0;
    if ((unsigned)d >= NN) d = 0;
    edges[e] = make_int2(s, d);
    atomicAdd(&degi[d], 1);
}

__global__ __launch_bounds__(1024) void k_scanA(const int* __restrict__ degi,
                                                int* __restrict__ chunksum) {
    __shared__ int s[1024];
    int i = blockIdx.x * 1024 + threadIdx.x;
    s[threadIdx.x] = (i < NN) ? degi[i] : 0;
    __syncthreads();
    for (int off = 512; off > 0; off >>= 1) {
        if (threadIdx.x < off) s[threadIdx.x] += s[threadIdx.x + off];
        __syncthreads();
    }
    if (threadIdx.x == 0) chunksum[blockIdx.x] = s[0];
}

__global__ void k_scanB(const int* __restrict__ chunksum, int* __restrict__ chunkoff) {
    __shared__ int s[128];
    int v = (threadIdx.x < NCHUNK) ? chunksum[threadIdx.x] : 0;
    s[threadIdx.x] = v;
    __syncthreads();
    for (int off = 1; off < 128; off <<= 1) {
        int t = (threadIdx.x >= off) ? s[threadIdx.x - off] : 0;
        __syncthreads();
        s[threadIdx.x] += t;
        __syncthreads();
    }
    if (threadIdx.x < NCHUNK) chunkoff[threadIdx.x] = s[threadIdx.x] - v;
}

__global__ __launch_bounds__(1024) void k_scanC(const int* __restrict__ degi,
                                                const int* __restrict__ chunkoff,
                                                int* __restrict__ rowstart,
                                                int* __restrict__ cursor,
                                                float* __restrict__ dinv) {
    __shared__ int s[1024];
    int i = blockIdx.x * 1024 + threadIdx.x;
    int v = (i < NN) ? degi[i] : 0;
    s[threadIdx.x] = v;
    __syncthreads();
    for (int off = 1; off < 1024; off <<= 1) {
        int t = (threadIdx.x >= off) ? s[threadIdx.x - off] : 0;
        __syncthreads();
        s[threadIdx.x] += t;
        __syncthreads();
    }
    if (i < NN) {
        int excl = s[threadIdx.x] - v + chunkoff[blockIdx.x];
        rowstart[i] = excl;
        cursor[i] = excl;
        dinv[i] = 1.0f / fmaxf((float)v, 1.0f);
    }
}

__global__ void k_scatter(const int2* __restrict__ edges, int nE,
                          int* __restrict__ cursor, int* __restrict__ srclist) {
    int e = blockIdx.x * blockDim.x + threadIdx.x;
    if (e >= nE) return;
    int2 ed = edges[e];
    int p = atomicAdd(&cursor[ed.y], 1);
    srclist[p] = ed.x;
}

// ---------------- gather kernels (MLP=2 unrolled) ----------------------------

__global__ __launch_bounds__(256) void k_gather1(
    const float4* __restrict__ feat, const int* __restrict__ rowstart,
    const int* __restrict__ degi, const int* __restrict__ srclist,
    const float* __restrict__ dinv, float4* __restrict__ out) {
    int node = blockIdx.x * 8 + (threadIdx.x >> 5);
    if (node >= NN) return;
    int lane = threadIdx.x & 31;
    int half = lane >> 4;
    int c = lane & 15;
    int beg = rowstart[node];
    int cnt = degi[node];
    float4 acc = make_float4(0.f, 0.f, 0.f, 0.f);
    float4 acc2 = make_float4(0.f, 0.f, 0.f, 0.f);
    int i = half;
    for (; i + 2 < cnt; i += 4) {
        int s0 = __ldg(&srclist[beg + i]);
        int s1 = __ldg(&srclist[beg + i + 2]);
        float4 v0 = __ldg(&feat[(long long)s0 * 16 + c]);
        float4 v1 = __ldg(&feat[(long long)s1 * 16 + c]);
        acc.x += v0.x; acc.y += v0.y; acc.z += v0.z; acc.w += v0.w;
        acc2.x += v1.x; acc2.y += v1.y; acc2.z += v1.z; acc2.w += v1.w;
    }
    for (; i < cnt; i += 2) {
        int s = __ldg(&srclist[beg + i]);
        float4 v = __ldg(&feat[(long long)s * 16 + c]);
        acc.x += v.x; acc.y += v.y; acc.z += v.z; acc.w += v.w;
    }
    acc.x += acc2.x; acc.y += acc2.y; acc.z += acc2.z; acc.w += acc2.w;
    acc.x += __shfl_xor_sync(0xffffffffu, acc.x, 16);
    acc.y += __shfl_xor_sync(0xffffffffu, acc.y, 16);
    acc.z += __shfl_xor_sync(0xffffffffu, acc.z, 16);
    acc.w += __shfl_xor_sync(0xffffffffu, acc.w, 16);
    if (half == 0) {
        float di = dinv[node];
        out[(long long)node * 16 + c] =
            make_float4(acc.x * di, acc.y * di, acc.z * di, acc.w * di);
    }
}

__global__ __launch_bounds__(256) void k_gather2(
    const float4* __restrict__ pfeat, const int* __restrict__ rowstart,
    const int* __restrict__ degi, const int* __restrict__ srclist,
    const float* __restrict__ dinv, const float4* __restrict__ s2,
    const float4* __restrict__ b2, float4* __restrict__ h2) {
    int node = blockIdx.x * 8 + (threadIdx.x >> 5);
    if (node >= NN) return;
    int lane = threadIdx.x & 31;
    int half = lane >> 4;
    int c = lane & 15;
    int beg = rowstart[node];
    int cnt = degi[node];
    float4 acc = make_float4(0.f, 0.f, 0.f, 0.f);
    float4 acc2 = make_float4(0.f, 0.f, 0.f, 0.f);
    int i = half;
    for (; i + 2 < cnt; i += 4) {
        int s0 = __ldg(&srclist[beg + i]);
        int s1 = __ldg(&srclist[beg + i + 2]);
        float4 v0 = __ldg(&pfeat[(long long)s0 * 16 + c]);
        float4 v1 = __ldg(&pfeat[(long long)s1 * 16 + c]);
        acc.x += v0.x; acc.y += v0.y; acc.z += v0.z; acc.w += v0.w;
        acc2.x += v1.x; acc2.y += v1.y; acc2.z += v1.z; acc2.w += v1.w;
    }
    for (; i < cnt; i += 2) {
        int s = __ldg(&srclist[beg + i]);
        float4 v = __ldg(&pfeat[(long long)s * 16 + c]);
        acc.x += v.x; acc.y += v.y; acc.z += v.z; acc.w += v.w;
    }
    acc.x += acc2.x; acc.y += acc2.y; acc.z += acc2.z; acc.w += acc2.w;
    acc.x += __shfl_xor_sync(0xffffffffu, acc.x, 16);
    acc.y += __shfl_xor_sync(0xffffffffu, acc.y, 16);
    acc.z += __shfl_xor_sync(0xffffffffu, acc.z, 16);
    acc.w += __shfl_xor_sync(0xffffffffu, acc.w, 16);
    if (half == 0) {
        float di = dinv[node];
        float4 sv = __ldg(&s2[(long long)node * 16 + c]);
        float4 bv = __ldg(&b2[c]);
        float4 r;
        r.x = fmaxf(sv.x + acc.x * di + bv.x, 0.f);
        r.y = fmaxf(sv.y + acc.y * di + bv.y, 0.f);
        r.z = fmaxf(sv.z + acc.z * di + bv.z, 0.f);
        r.w = fmaxf(sv.w + acc.w * di + bv.w, 0.f);
        h2[(long long)node * 16 + c] = r;
    }
}

// ---------------- GEMM kernels (R7 exact: 32 nodes/block, 128 threads) -------

__global__ __launch_bounds__(128) void k_layer1(
    const float* __restrict__ x, const float* __restrict__ agg,
    const float* __restrict__ Wself, const float* __restrict__ Wneigh,
    const float* __restrict__ b, float* __restrict__ h1) {
    __shared__ float sW[INC * HIDC];   // 32 KB: [k][j] 64x128
    __shared__ float sF[32 * INC];     // 8 KB : [n][k] 32x64
    const int tid = threadIdx.x;
    const int lane = tid & 31;
    const int wrp = tid >> 5;
    const int j0 = lane * 4;
    const int nb = wrp * 8;
    const int n0 = blockIdx.x * 32;

    float4 acc[8];
#pragma unroll
    for (int n = 0; n < 8; n++) acc[n] = make_float4(0.f, 0.f, 0.f, 0.f);

#pragma unroll
    for (int pass = 0; pass < 2; pass++) {
        const float* W = pass ? Wneigh : Wself;
        const float* F = pass ? agg : x;
        if (pass) __syncthreads();
        for (int i = tid; i < INC * HIDC / 4; i += 128)
            ((float4*)sW)[i] = ((const float4*)W)[i];
        {
            const float4* fr = (const float4*)(F + (long long)n0 * INC);
            for (int i = tid; i < 32 * INC / 4; i += 128) ((float4*)sF)[i] = fr[i];
        }
        __syncthreads();
#pragma unroll 4
        for (int k4 = 0; k4 < 16; k4++) {
            float4 w0 = *(const float4*)&sW[(k4 * 4 + 0) * HIDC + j0];
            float4 w1 = *(const float4*)&sW[(k4 * 4 + 1) * HIDC + j0];
            float4 w2 = *(const float4*)&sW[(k4 * 4 + 2) * HIDC + j0];
            float4 w3 = *(const float4*)&sW[(k4 * 4 + 3) * HIDC + j0];
#pragma unroll
            for (int n = 0; n < 8; n++) {
                float4 f = *(const float4*)&sF[(nb + n) * INC + k4 * 4];
                acc[n].x = fmaf(f.x, w0.x, acc[n].x);
                acc[n].y = fmaf(f.x, w0.y, acc[n].y);
                acc[n].z = fmaf(f.x, w0.z, acc[n].z);
                acc[n].w = fmaf(f.x, w0.w, acc[n].w);
                acc[n].x = fmaf(f.y, w1.x, acc[n].x);
                acc[n].y = fmaf(f.y, w1.y, acc[n].y);
                acc[n].z = fmaf(f.y, w1.z, acc[n].z);
                acc[n].w = fmaf(f.y, w1.w, acc[n].w);
                acc[n].x = fmaf(f.z, w2.x, acc[n].x);
                acc[n].y = fmaf(f.z, w2.y, acc[n].y);
                acc[n].z = fmaf(f.z, w2.z, acc[n].z);
                acc[n].w = fmaf(f.z, w2.w, acc[n].w);
                acc[n].x = fmaf(f.w, w3.x, acc[n].x);
                acc[n].y = fmaf(f.w, w3.y, acc[n].y);
                acc[n].z = fmaf(f.w, w3.z, acc[n].z);
                acc[n].w = fmaf(f.w, w3.w, acc[n].w);
            }
        }
    }
    float4 bv = *(const float4*)&b[j0];
#pragma unroll
    for (int n = 0; n < 8; n++) {
        float4 r;
        r.x = fmaxf(acc[n].x + bv.x, 0.f);
        r.y = fmaxf(acc[n].y + bv.y, 0.f);
        r.z = fmaxf(acc[n].z + bv.z, 0.f);
        r.w = fmaxf(acc[n].w + bv.w, 0.f);
        *(float4*)&h1[((long long)(n0 + nb + n)) * HIDC + j0] = r;
    }
}

__global__ __launch_bounds__(128) void k_dual(
    const float* __restrict__ h1,
    const float* __restrict__ Wself2, const float* __restrict__ Wneigh2,
    float* __restrict__ s2, float* __restrict__ p) {
    __shared__ float sW[64 * 128];     // 32 KB: [kk][jv] for current k-slice
    __shared__ float sF[32 * 64];      // 8 KB : [n][kk]
    const int tid = threadIdx.x;
    const int lane = tid & 31;
    const int wrp = tid >> 5;
    const int j0 = lane * 4;           // virtual col (all 4 in same matrix)
    const int nb = wrp * 8;
    const int n0 = blockIdx.x * 32;

    float4 acc[8];
#pragma unroll
    for (int n = 0; n < 8; n++) acc[n] = make_float4(0.f, 0.f, 0.f, 0.f);

#pragma unroll
    for (int kp = 0; kp < 2; kp++) {
        if (kp) __syncthreads();
        for (int i = tid * 4; i < 64 * 128; i += 128 * 4) {
            int kk = i >> 7, jv = i & 127;
            const float* W = (jv < 64) ? Wself2 : Wneigh2;
            *(float4*)&sW[i] = *(const float4*)&W[(kp * 64 + kk) * OUTC + (jv & 63)];
        }
        for (int i = tid * 4; i < 32 * 64; i += 128 * 4) {
            int n = i >> 6, kk = i & 63;
            *(float4*)&sF[i] = *(const float4*)&h1[((long long)(n0 + n)) * HIDC + kp * 64 + kk];
        }
        __syncthreads();
#pragma unroll 4
        for (int k4 = 0; k4 < 16; k4++) {
            float4 w0 = *(const float4*)&sW[(k4 * 4 + 0) * 128 + j0];
            float4 w1 = *(const float4*)&sW[(k4 * 4 + 1) * 128 + j0];
            float4 w2 = *(const float4*)&sW[(k4 * 4 + 2) * 128 + j0];
            float4 w3 = *(const float4*)&sW[(k4 * 4 + 3) * 128 + j0];
#pragma unroll
            for (int n = 0; n < 8; n++) {
                float4 f = *(const float4*)&sF[(nb + n) * 64 + k4 * 4];
                acc[n].x = fmaf(f.x, w0.x, acc[n].x);
                acc[n].y = fmaf(f.x, w0.y, acc[n].y);
                acc[n].z = fmaf(f.x, w0.z, acc[n].z);
                acc[n].w = fmaf(f.x, w0.w, acc[n].w);
                acc[n].x = fmaf(f.y, w1.x, acc[n].x);
                acc[n].y = fmaf(f.y, w1.y, acc[n].y);
                acc[n].z = fmaf(f.y, w1.z, acc[n].z);
                acc[n].w = fmaf(f.y, w1.w, acc[n].w);
                acc[n].x = fmaf(f.z, w2.x, acc[n].x);
                acc[n].y = fmaf(f.z, w2.y, acc[n].y);
                acc[n].z = fmaf(f.z, w2.z, acc[n].z);
                acc[n].w = fmaf(f.z, w2.w, acc[n].w);
                acc[n].x = fmaf(f.w, w3.x, acc[n].x);
                acc[n].y = fmaf(f.w, w3.y, acc[n].y);
                acc[n].z = fmaf(f.w, w3.z, acc[n].z);
                acc[n].w = fmaf(f.w, w3.w, acc[n].w);
            }
        }
    }
    float* dst = (j0 < 64) ? s2 : p;
    int jd = j0 & 63;
#pragma unroll
    for (int n = 0; n < 8; n++)
        *(float4*)&dst[((long long)(n0 + nb + n)) * OUTC + jd] = acc[n];
}

// classifier: out = h2 @ wc + bc
__global__ __launch_bounds__(256) void k_out(const float* __restrict__ h2,
                                             const float* __restrict__ wc,
                                             const float* __restrict__ bc,
                                             float* __restrict__ out) {
    __shared__ float sW[OUTC * NCLS];
    __shared__ float sB[NCLS];
    __shared__ float sH[12 * 65];
    const int tid = threadIdx.x;
    const int n0 = blockIdx.x * 12;
    const int nmax = min(12, NN - n0);
    for (int i = tid; i < OUTC * NCLS; i += 256) sW[i] = wc[i];
    if (tid < NCLS) sB[tid] = bc[tid];
    for (int i = tid; i < nmax * OUTC; i += 256) {
        int ln = i >> 6, k = i & 63;
        sH[ln * 65 + k] = h2[(long long)(n0 + ln) * OUTC + k];
    }
    __syncthreads();
    if (tid < 240) {
        int ln = tid / 20, c = tid % 20;
        if (ln < nmax) {
            float acc = sB[c];
#pragma unroll
            for (int k = 0; k < OUTC; k++)
                acc = fmaf(sH[ln * 65 + k], sW[k * NCLS + c], acc);
            out[(long long)(n0 + ln) * NCLS + c] = acc;
        }
    }
}

// ---------------- launch ----------------------------------------------------
extern "C" void kernel_launch(void* const* d_in, const int* in_sizes, int n_in,
                              void* d_out, int out_size) {
    const float* x   = (const float*)d_in[0];
    const void*  ei  = d_in[1];
    const float* ws1 = (const float*)d_in[2];
    const float* wn1 = (const float*)d_in[3];
    const float* b1  = (const float*)d_in[4];
    const float* ws2 = (const float*)d_in[5];
    const float* wn2 = (const float*)d_in[6];
    const float* b2  = (const float*)d_in[7];
    const float* wc  = (const float*)d_in[8];
    const float* bc  = (const float*)d_in[9];
    float* out = (float*)d_out;

    int nE = in_sizes[1] / 2;
    if (nE > NE_MAX) nE = NE_MAX;

    void *p_flag, *p_edges, *p_degi, *p_rs, *p_cur, *p_src, *p_cs, *p_co;
    void *p_dinv, *p_agg1, *p_h1, *p_pp, *p_s2, *p_h2;
    cudaGetSymbolAddress(&p_flag, g_is64);
    cudaGetSymbolAddress(&p_edges, g_edges);
    cudaGetSymbolAddress(&p_degi, g_degi);
    cudaGetSymbolAddress(&p_rs,   g_rowstart);
    cudaGetSymbolAddress(&p_cur,  g_cursor);
    cudaGetSymbolAddress(&p_src,  g_srclist);
    cudaGetSymbolAddress(&p_cs,   g_chunksum);
    cudaGetSymbolAddress(&p_co,   g_chunkoff);
    cudaGetSymbolAddress(&p_dinv, g_dinv);
    cudaGetSymbolAddress(&p_agg1, g_agg1);
    cudaGetSymbolAddress(&p_h1,   g_h1);
    cudaGetSymbolAddress(&p_pp,   g_p);
    cudaGetSymbolAddress(&p_s2,   g_s2);
    cudaGetSymbolAddress(&p_h2,   g_h2);
    int*   flag  = (int*)p_flag;
    int2*  edges = (int2*)p_edges;
    int*   degi  = (int*)p_degi;
    int*   rs    = (int*)p_rs;
    int*   cur   = (int*)p_cur;
    int*   src   = (int*)p_src;
    int*   cs    = (int*)p_cs;
    int*   co    = (int*)p_co;
    float* dinv  = (float*)p_dinv;
    float* agg1  = (float*)p_agg1;
    float* h1    = (float*)p_h1;
    float* pp    = (float*)p_pp;
    float* s2    = (float*)p_s2;
    float* h2    = (float*)p_h2;

    // dtype detect + CSR build
    k_detect<<<1, 256>>>((const int*)ei, in_sizes[1], flag);
    k_zero_deg<<<(NN + 255) / 256, 256>>>(degi);
    k_convert<<<(nE + 255) / 256, 256>>>(ei, nE, edges, degi, flag);
    k_scanA<<<NCHUNK, 1024>>>(degi, cs);
    k_scanB<<<1, 128>>>(cs, co);
    k_scanC<<<NCHUNK, 1024>>>(degi, co, rs, cur, dinv);
    k_scatter<<<(nE + 255) / 256, 256>>>(edges, nE, cur, src);

    // layer 1
    k_gather1<<<(NN + 7) / 8, 256>>>((const float4*)x, rs, degi, src, dinv,
                                     (float4*)agg1);
    k_layer1<<<NN / 32, 128>>>(x, agg1, ws1, wn1, b1, h1);

    // layer 2
    k_dual<<<NN / 32, 128>>>(h1, ws2, wn2, s2, pp);
    k_gather2<<<(NN + 7) / 8, 256>>>((const float4*)pp, rs, degi, src, dinv,
                                     (const float4*)s2, (const float4*)b2,
                                     (float4*)h2);

    // classifier
    k_out<<<(NN + 11) / 12, 256>>>(h2, wc, bc, out);
}

// round 11
// speedup vs baseline: 2.1811x; 1.2441x over previous
#include <cuda_runtime.h>
#include <cuda_bf16.h>

#define NN 100000
#define NE_MAX 1600000
#define INC 64
#define HIDC 128
#define OUTC 64
#define NCLS 20
#define NCHUNK 98          // ceil(NN/1024)

// ---------------- device scratch (static globals; no allocation) ------------
__device__ int   g_is64;
__device__ __align__(16) int2 g_edges[NE_MAX];
__device__ int   g_degi[NN];
__device__ int   g_rowstart[NN];
__device__ int   g_cursor[NN];
__device__ int   g_srclist[NE_MAX];
__device__ int   g_chunksum[NCHUNK];
__device__ int   g_chunkoff[NCHUNK];
__device__ float g_dinv[NN];
__device__ __align__(16) float g_agg1[(size_t)NN * INC];
__device__ __align__(16) float g_h1[(size_t)NN * HIDC];
__device__ __align__(16) float g_sp[(size_t)NN * HIDC];  // [s2 | p] 128 wide
__device__ __align__(16) float g_h2[(size_t)NN * OUTC];

// ---------------- tf32 mma helpers -------------------------------------------

__device__ __forceinline__ unsigned f2tf32(float f) {
    unsigned r; asm("cvt.rna.tf32.f32 %0, %1;" : "=r"(r) : "f"(f)); return r;
}

__device__ __forceinline__ void mma_tf32(float4& d,
                                         unsigned a0, unsigned a1, unsigned a2, unsigned a3,
                                         unsigned b0, unsigned b1) {
    asm("mma.sync.aligned.m16n8k8.row.col.f32.tf32.tf32.f32 "
        "{%0,%1,%2,%3}, {%4,%5,%6,%7}, {%8,%9}, {%0,%1,%2,%3};"
        : "+f"(d.x), "+f"(d.y), "+f"(d.z), "+f"(d.w)
        : "r"(a0), "r"(a1), "r"(a2), "r"(a3), "r"(b0), "r"(b1));
}

// ---------------- CSR build kernels -----------------------------------------

__global__ void k_detect(const int* __restrict__ ei32, int n32, int* __restrict__ flag) {
    __shared__ int s_any;
    if (threadIdx.x == 0) s_any = 0;
    __syncthreads();
    int nonzero = 0;
    int limit = n32 < 16384 ? n32 : 16384;
    for (int i = 1 + 2 * threadIdx.x; i < limit; i += 2 * blockDim.x)
        if (ei32[i] != 0) nonzero = 1;
    if (nonzero) atomicOr(&s_any, 1);
    __syncthreads();
    if (threadIdx.x == 0) *flag = (s_any == 0) ? 1 : 0;  // all-zero odd words -> int64
}

__global__ void k_zero_deg(int* __restrict__ degi) {
    int i = blockIdx.x * blockDim.x + threadIdx.x;
    if (i < NN) degi[i] = 0;
}

__global__ void k_convert(const void* __restrict__ ei, int nE, int2* __restrict__ edges,
                          int* __restrict__ degi, const int* __restrict__ flag) {
    int e = blockIdx.x * blockDim.x + threadIdx.x;
    if (e >= nE) return;
    int s, d;
    if (*flag) {
        s = (int)((const long long*)ei)[e];
        d = (int)((const long long*)ei)[(long long)nE + e];
    } else {
        s = ((const int*)ei)[e];
        d = ((const int*)ei)[nE + e];
    }
    if ((unsigned)s >= NN) s = 0;
    if ((unsigned)d >= NN) d = 0;
    edges[e] = make_int2(s, d);
    atomicAdd(&degi[d], 1);
}

__global__ __launch_bounds__(1024) void k_scanA(const int* __restrict__ degi,
                                                int* __restrict__ chunksum) {
    __shared__ int s[1024];
    int i = blockIdx.x * 1024 + threadIdx.x;
    s[threadIdx.x] = (i < NN) ? degi[i] : 0;
    __syncthreads();
    for (int off = 512; off > 0; off >>= 1) {
        if (threadIdx.x < off) s[threadIdx.x] += s[threadIdx.x + off];
        __syncthreads();
    }
    if (threadIdx.x == 0) chunksum[blockIdx.x] = s[0];
}

__global__ void k_scanB(const int* __restrict__ chunksum, int* __restrict__ chunkoff) {
    __shared__ int s[128];
    int v = (threadIdx.x < NCHUNK) ? chunksum[threadIdx.x] : 0;
    s[threadIdx.x] = v;
    __syncthreads();
    for (int off = 1; off < 128; off <<= 1) {
        int t = (threadIdx.x >= off) ? s[threadIdx.x - off] : 0;
        __syncthreads();
        s[threadIdx.x] += t;
        __syncthreads();
    }
    if (threadIdx.x < NCHUNK) chunkoff[threadIdx.x] = s[threadIdx.x] - v;
}

__global__ __launch_bounds__(1024) void k_scanC(const int* __restrict__ degi,
                                                const int* __restrict__ chunkoff,
                                                int* __restrict__ rowstart,
                                                int* __restrict__ cursor,
                                                float* __restrict__ dinv) {
    __shared__ int s[1024];
    int i = blockIdx.x * 1024 + threadIdx.x;
    int v = (i < NN) ? degi[i] : 0;
    s[threadIdx.x] = v;
    __syncthreads();
    for (int off = 1; off < 1024; off <<= 1) {
        int t = (threadIdx.x >= off) ? s[threadIdx.x - off] : 0;
        __syncthreads();
        s[threadIdx.x] += t;
        __syncthreads();
    }
    if (i < NN) {
        int excl = s[threadIdx.x] - v + chunkoff[blockIdx.x];
        rowstart[i] = excl;
        cursor[i] = excl;
        dinv[i] = 1.0f / fmaxf((float)v, 1.0f);
    }
}

__global__ void k_scatter(const int2* __restrict__ edges, int nE,
                          int* __restrict__ cursor, int* __restrict__ srclist) {
    int e = blockIdx.x * blockDim.x + threadIdx.x;
    if (e >= nE) return;
    int2 ed = edges[e];
    int p = atomicAdd(&cursor[ed.y], 1);
    srclist[p] = ed.x;
}

// ---------------- gather kernels ---------------------------------------------

__global__ __launch_bounds__(256) void k_gather1(
    const float4* __restrict__ feat, const int* __restrict__ rowstart,
    const int* __restrict__ degi, const int* __restrict__ srclist,
    const float* __restrict__ dinv, float4* __restrict__ out) {
    int node = blockIdx.x * 8 + (threadIdx.x >> 5);
    if (node >= NN) return;
    int lane = threadIdx.x & 31;
    int half = lane >> 4;
    int c = lane & 15;
    int beg = rowstart[node];
    int cnt = degi[node];
    float4 acc = make_float4(0.f, 0.f, 0.f, 0.f);
    float4 acc2 = make_float4(0.f, 0.f, 0.f, 0.f);
    int i = half;
    for (; i + 2 < cnt; i += 4) {
        int s0 = __ldg(&srclist[beg + i]);
        int s1 = __ldg(&srclist[beg + i + 2]);
        float4 v0 = __ldg(&feat[(long long)s0 * 16 + c]);
        float4 v1 = __ldg(&feat[(long long)s1 * 16 + c]);
        acc.x += v0.x; acc.y += v0.y; acc.z += v0.z; acc.w += v0.w;
        acc2.x += v1.x; acc2.y += v1.y; acc2.z += v1.z; acc2.w += v1.w;
    }
    for (; i < cnt; i += 2) {
        int s = __ldg(&srclist[beg + i]);
        float4 v = __ldg(&feat[(long long)s * 16 + c]);
        acc.x += v.x; acc.y += v.y; acc.z += v.z; acc.w += v.w;
    }
    acc.x += acc2.x; acc.y += acc2.y; acc.z += acc2.z; acc.w += acc2.w;
    acc.x += __shfl_xor_sync(0xffffffffu, acc.x, 16);
    acc.y += __shfl_xor_sync(0xffffffffu, acc.y, 16);
    acc.z += __shfl_xor_sync(0xffffffffu, acc.z, 16);
    acc.w += __shfl_xor_sync(0xffffffffu, acc.w, 16);
    if (half == 0) {
        float di = dinv[node];
        out[(long long)node * 16 + c] =
            make_float4(acc.x * di, acc.y * di, acc.z * di, acc.w * di);
    }
}

// gather over p (= sp cols 64..127) + epilogue: h2 = relu(s2 + agg*dinv + b2)
__global__ __launch_bounds__(256) void k_gather2(
    const float4* __restrict__ sp, const int* __restrict__ rowstart,
    const int* __restrict__ degi, const int* __restrict__ srclist,
    const float* __restrict__ dinv,
    const float4* __restrict__ b2, float4* __restrict__ h2) {
    int node = blockIdx.x * 8 + (threadIdx.x >> 5);
    if (node >= NN) return;
    int lane = threadIdx.x & 31;
    int half = lane >> 4;
    int c = lane & 15;
    int beg = rowstart[node];
    int cnt = degi[node];
    float4 acc = make_float4(0.f, 0.f, 0.f, 0.f);
    float4 acc2 = make_float4(0.f, 0.f, 0.f, 0.f);
    int i = half;
    for (; i + 2 < cnt; i += 4) {
        int s0 = __ldg(&srclist[beg + i]);
        int s1 = __ldg(&srclist[beg + i + 2]);
        float4 v0 = __ldg(&sp[(long long)s0 * 32 + 16 + c]);
        float4 v1 = __ldg(&sp[(long long)s1 * 32 + 16 + c]);
        acc.x += v0.x; acc.y += v0.y; acc.z += v0.z; acc.w += v0.w;
        acc2.x += v1.x; acc2.y += v1.y; acc2.z += v1.z; acc2.w += v1.w;
    }
    for (; i < cnt; i += 2) {
        int s = __ldg(&srclist[beg + i]);
        float4 v = __ldg(&sp[(long long)s * 32 + 16 + c]);
        acc.x += v.x; acc.y += v.y; acc.z += v.z; acc.w += v.w;
    }
    acc.x += acc2.x; acc.y += acc2.y; acc.z += acc2.z; acc.w += acc2.w;
    acc.x += __shfl_xor_sync(0xffffffffu, acc.x, 16);
    acc.y += __shfl_xor_sync(0xffffffffu, acc.y, 16);
    acc.z += __shfl_xor_sync(0xffffffffu, acc.z, 16);
    acc.w += __shfl_xor_sync(0xffffffffu, acc.w, 16);
    if (half == 0) {
        float di = dinv[node];
        float4 sv = __ldg(&sp[(long long)node * 32 + c]);
        float4 bv = __ldg(&b2[c]);
        float4 r;
        r.x = fmaxf(sv.x + acc.x * di + bv.x, 0.f);
        r.y = fmaxf(sv.y + acc.y * di + bv.y, 0.f);
        r.z = fmaxf(sv.z + acc.z * di + bv.z, 0.f);
        r.w = fmaxf(sv.w + acc.w * di + bv.w, 0.f);
        h2[(long long)node * 16 + c] = r;
    }
}

// ---------------- tf32 tensor-core GEMM: C[M x 128] = A[M x 128] @ W[128 x 128]
// MODE 0 (layer1): A = [A0 | A1] k-split (x | agg1), W rows k<64 from W0 (Ws1),
//                  k>=64 from W1 (Wn1), both 64x128 row-major. relu(+bias).
// MODE 1 (layer2): A0 = h1, A1 = h1+64 (same buffer), W cols j<64 from W0 (Ws2),
//                  j>=64 from W1 (Wn2), both 128x64 row-major. plain store.
#define SA_S 36
#define SW_S 136
template<int MODE>
__global__ __launch_bounds__(256) void k_gemm(
    const float* __restrict__ A0, int lda0,
    const float* __restrict__ A1, int lda1,
    const float* __restrict__ W0, const float* __restrict__ W1,
    const float* __restrict__ bias, float* __restrict__ out) {
    __shared__ unsigned sA[128 * SA_S];   // 18.4 KB (tf32 bits)
    __shared__ unsigned sW[32 * SW_S];    // 17.4 KB
    const int tid = threadIdx.x;
    const int lane = tid & 31;
    const int wrp = tid >> 5;             // 0..7
    const int gid = lane >> 2;            // 0..7
    const int tig = lane & 3;             // 0..3
    const int wm = wrp * 16;              // warp row base in tile
    const int n0 = blockIdx.x * 128;

    float4 acc[16];
#pragma unroll
    for (int t = 0; t < 16; t++) acc[t] = make_float4(0.f, 0.f, 0.f, 0.f);

    for (int kp = 0; kp < 4; kp++) {
        if (kp) __syncthreads();
        // load A tile: 128 rows x 32 cols (global k = kp*32)
        {
            const float* Asrc = (kp < 2) ? A0 : A1;
            int lda = (kp < 2) ? lda0 : lda1;
            int colbase = (kp & 1) * 32;
#pragma unroll
            for (int t = 0; t < 4; t++) {
                int idx = tid + t * 256;        // 0..1023 float4
                int row = idx >> 3;
                int c4 = idx & 7;
                int grow = n0 + row; if (grow >= NN) grow = NN - 1;
                float4 v = __ldg((const float4*)&Asrc[(long long)grow * lda + colbase + c4 * 4]);
                uint4 u;
                u.x = f2tf32(v.x); u.y = f2tf32(v.y);
                u.z = f2tf32(v.z); u.w = f2tf32(v.w);
                *(uint4*)&sA[row * SA_S + c4 * 4] = u;
            }
        }
        // load W tile: 32 rows (k) x 128 cols
        {
#pragma unroll
            for (int t = 0; t < 4; t++) {
                int idx = tid + t * 256;        // 0..1023 float4
                int kk = idx >> 5;              // 32 float4 per row
                int c4 = idx & 31;
                int kglob = kp * 32 + kk;
                float4 v;
                if (MODE == 0) {
                    const float* Wsrc = (kglob < 64) ? (W0 + (long long)kglob * 128)
                                                     : (W1 + (long long)(kglob - 64) * 128);
                    v = __ldg((const float4*)&Wsrc[c4 * 4]);
                } else {
                    const float* Wsrc = (c4 < 16) ? (W0 + (long long)kglob * 64 + c4 * 4)
                                                  : (W1 + (long long)kglob * 64 + (c4 - 16) * 4);
                    v = __ldg((const float4*)Wsrc);
                }
                uint4 u;
                u.x = f2tf32(v.x); u.y = f2tf32(v.y);
                u.z = f2tf32(v.z); u.w = f2tf32(v.w);
                *(uint4*)&sW[kk * SW_S + c4 * 4] = u;
            }
        }
        __syncthreads();
#pragma unroll
        for (int ks = 0; ks < 4; ks++) {
            unsigned a0 = sA[(wm + gid) * SA_S + ks * 8 + tig];
            unsigned a1 = sA[(wm + gid + 8) * SA_S + ks * 8 + tig];
            unsigned a2 = sA[(wm + gid) * SA_S + ks * 8 + tig + 4];
            unsigned a3 = sA[(wm + gid + 8) * SA_S + ks * 8 + tig + 4];
#pragma unroll
            for (int nt = 0; nt < 16; nt++) {
                unsigned b0 = sW[(ks * 8 + tig) * SW_S + nt * 8 + gid];
                unsigned b1 = sW[(ks * 8 + tig + 4) * SW_S + nt * 8 + gid];
                mma_tf32(acc[nt], a0, a1, a2, a3, b0, b1);
            }
        }
    }

    // epilogue: c0,c1 -> (row0, col..col+1); c2,c3 -> (row0+8, col..col+1)
    int row0 = n0 + wm + gid;
    int row1 = row0 + 8;
#pragma unroll
    for (int nt = 0; nt < 16; nt++) {
        int col = nt * 8 + 2 * tig;
        float2 lo = make_float2(acc[nt].x, acc[nt].y);
        float2 hi = make_float2(acc[nt].z, acc[nt].w);
        if (MODE == 0) {
            float2 bb = __ldg((const float2*)&bias[col]);
            lo.x = fmaxf(lo.x + bb.x, 0.f); lo.y = fmaxf(lo.y + bb.y, 0.f);
            hi.x = fmaxf(hi.x + bb.x, 0.f); hi.y = fmaxf(hi.y + bb.y, 0.f);
        }
        if (row0 < NN) *(float2*)&out[(long long)row0 * 128 + col] = lo;
        if (row1 < NN) *(float2*)&out[(long long)row1 * 128 + col] = hi;
    }
}

// classifier: out = h2 @ wc + bc
__global__ __launch_bounds__(256) void k_out(const float* __restrict__ h2,
                                             const float* __restrict__ wc,
                                             const float* __restrict__ bc,
                                             float* __restrict__ out) {
    __shared__ float sW[OUTC * NCLS];
    __shared__ float sB[NCLS];
    __shared__ float sH[12 * 65];
    const int tid = threadIdx.x;
    const int n0 = blockIdx.x * 12;
    const int nmax = min(12, NN - n0);
    for (int i = tid; i < OUTC * NCLS; i += 256) sW[i] = wc[i];
    if (tid < NCLS) sB[tid] = bc[tid];
    for (int i = tid; i < nmax * OUTC; i += 256) {
        int ln = i >> 6, k = i & 63;
        sH[ln * 65 + k] = h2[(long long)(n0 + ln) * OUTC + k];
    }
    __syncthreads();
    if (tid < 240) {
        int ln = tid / 20, c = tid % 20;
        if (ln < nmax) {
            float acc = sB[c];
#pragma unroll
            for (int k = 0; k < OUTC; k++)
                acc = fmaf(sH[ln * 65 + k], sW[k * NCLS + c], acc);
            out[(long long)(n0 + ln) * NCLS + c] = acc;
        }
    }
}

// ---------------- launch ----------------------------------------------------
extern "C" void kernel_launch(void* const* d_in, const int* in_sizes, int n_in,
                              void* d_out, int out_size) {
    const float* x   = (const float*)d_in[0];
    const void*  ei  = d_in[1];
    const float* ws1 = (const float*)d_in[2];
    const float* wn1 = (const float*)d_in[3];
    const float* b1  = (const float*)d_in[4];
    const float* ws2 = (const float*)d_in[5];
    const float* wn2 = (const float*)d_in[6];
    const float* b2  = (const float*)d_in[7];
    const float* wc  = (const float*)d_in[8];
    const float* bc  = (const float*)d_in[9];
    float* out = (float*)d_out;

    int nE = in_sizes[1] / 2;
    if (nE > NE_MAX) nE = NE_MAX;

    void *p_flag, *p_edges, *p_degi, *p_rs, *p_cur, *p_src, *p_cs, *p_co;
    void *p_dinv, *p_agg1, *p_h1, *p_sp, *p_h2;
    cudaGetSymbolAddress(&p_flag, g_is64);
    cudaGetSymbolAddress(&p_edges, g_edges);
    cudaGetSymbolAddress(&p_degi, g_degi);
    cudaGetSymbolAddress(&p_rs,   g_rowstart);
    cudaGetSymbolAddress(&p_cur,  g_cursor);
    cudaGetSymbolAddress(&p_src,  g_srclist);
    cudaGetSymbolAddress(&p_cs,   g_chunksum);
    cudaGetSymbolAddress(&p_co,   g_chunkoff);
    cudaGetSymbolAddress(&p_dinv, g_dinv);
    cudaGetSymbolAddress(&p_agg1, g_agg1);
    cudaGetSymbolAddress(&p_h1,   g_h1);
    cudaGetSymbolAddress(&p_sp,   g_sp);
    cudaGetSymbolAddress(&p_h2,   g_h2);
    int*   flag  = (int*)p_flag;
    int2*  edges = (int2*)p_edges;
    int*   degi  = (int*)p_degi;
    int*   rs    = (int*)p_rs;
    int*   cur   = (int*)p_cur;
    int*   src   = (int*)p_src;
    int*   cs    = (int*)p_cs;
    int*   co    = (int*)p_co;
    float* dinv  = (float*)p_dinv;
    float* agg1  = (float*)p_agg1;
    float* h1    = (float*)p_h1;
    float* sp    = (float*)p_sp;
    float* h2    = (float*)p_h2;

    // dtype detect + CSR build
    k_detect<<<1, 256>>>((const int*)ei, in_sizes[1], flag);
    k_zero_deg<<<(NN + 255) / 256, 256>>>(degi);
    k_convert<<<(nE + 255) / 256, 256>>>(ei, nE, edges, degi, flag);
    k_scanA<<<NCHUNK, 1024>>>(degi, cs);
    k_scanB<<<1, 128>>>(cs, co);
    k_scanC<<<NCHUNK, 1024>>>(degi, co, rs, cur, dinv);
    k_scatter<<<(nE + 255) / 256, 256>>>(edges, nE, cur, src);

    const int gemm_blocks = (NN + 127) / 128;

    // layer 1: gather-agg, then tf32 GEMM (relu + bias)
    k_gather1<<<(NN + 7) / 8, 256>>>((const float4*)x, rs, degi, src, dinv,
                                     (float4*)agg1);
    k_gemm<0><<<gemm_blocks, 256>>>(x, INC, agg1, INC, ws1, wn1, b1, h1);

    // layer 2: tf32 GEMM into sp = [s2 | p], then gather+epilogue
    k_gemm<1><<<gemm_blocks, 256>>>(h1, HIDC, h1 + 64, HIDC, ws2, wn2, nullptr, sp);
    k_gather2<<<(NN + 7) / 8, 256>>>((const float4*)sp, rs, degi, src, dinv,
                                     (const float4*)b2, (float4*)h2);

    // classifier
    k_out<<<(NN + 11) / 12, 256>>>(h2, wc, bc, out);
}

// round 12
// speedup vs baseline: 2.3400x; 1.0729x over previous
#include <cuda_runtime.h>
#include <cuda_bf16.h>

#define NN 100000
#define NE_MAX 1600000
#define INC 64
#define HIDC 128
#define OUTC 64
#define NCLS 20
#define NCHUNK 98          // ceil(NN/1024)

// ---------------- device scratch (static globals; no allocation) ------------
__device__ int   g_is64;
__device__ int   g_degi[NN];
__device__ int   g_rowstart[NN];
__device__ int   g_cursor[NN];
__device__ int   g_srclist[NE_MAX];
__device__ int   g_chunksum[NCHUNK];
__device__ int   g_chunkoff[NCHUNK];
__device__ float g_dinv[NN];
__device__ __align__(16) float g_xt[(size_t)NN * INC];     // tf32-rounded x
__device__ __align__(16) float g_agg1[(size_t)NN * INC];   // tf32-rounded agg*dinv
__device__ __align__(16) float g_h1[(size_t)NN * HIDC];    // tf32-rounded h1
__device__ __align__(16) float g_sp[(size_t)NN * HIDC];    // [s2 | p] fp32
__device__ __align__(16) float g_h2[(size_t)NN * OUTC];
__device__ __align__(16) float g_wcat1[HIDC * HIDC];       // tf32 [Ws1;Wn1]
__device__ __align__(16) float g_wcat2[HIDC * HIDC];       // tf32 [Ws2|Wn2]

// ---------------- helpers ----------------------------------------------------

__device__ __forceinline__ unsigned f2tf32(float f) {
    unsigned r; asm("cvt.rna.tf32.f32 %0, %1;" : "=r"(r) : "f"(f)); return r;
}
__device__ __forceinline__ float ftf(float f) { return __uint_as_float(f2tf32(f)); }

__device__ __forceinline__ void mma_tf32(float4& d,
                                         unsigned a0, unsigned a1, unsigned a2, unsigned a3,
                                         unsigned b0, unsigned b1) {
    asm("mma.sync.aligned.m16n8k8.row.col.f32.tf32.tf32.f32 "
        "{%0,%1,%2,%3}, {%4,%5,%6,%7}, {%8,%9}, {%0,%1,%2,%3};"
        : "+f"(d.x), "+f"(d.y), "+f"(d.z), "+f"(d.w)
        : "r"(a0), "r"(a1), "r"(a2), "r"(a3), "r"(b0), "r"(b1));
}

__device__ __forceinline__ void cp16(void* smem, const void* g) {
    unsigned s = (unsigned)__cvta_generic_to_shared(smem);
    asm volatile("cp.async.cg.shared.global [%0], [%1], 16;" :: "r"(s), "l"(g));
}
__device__ __forceinline__ void cp_commit() { asm volatile("cp.async.commit_group;"); }
__device__ __forceinline__ void cp_wait1()  { asm volatile("cp.async.wait_group 1;" ::: "memory"); }
__device__ __forceinline__ void cp_wait0()  { asm volatile("cp.async.wait_group 0;" ::: "memory"); }

// ---------------- init / prep kernels ----------------------------------------

// detect dtype (block 0) + zero degi (all blocks)
__global__ void k_init(const int* __restrict__ ei32, int n32,
                       int* __restrict__ flag, int* __restrict__ degi) {
    int i = blockIdx.x * blockDim.x + threadIdx.x;
    if (i < NN) degi[i] = 0;
    if (blockIdx.x == 0) {
        __shared__ int s_any;
        if (threadIdx.x == 0) s_any = 0;
        __syncthreads();
        int nonzero = 0;
        int limit = n32 < 16384 ? n32 : 16384;
        for (int k = 1 + 2 * threadIdx.x; k < limit; k += 2 * blockDim.x)
            if (ei32[k] != 0) nonzero = 1;
        if (nonzero) atomicOr(&s_any, 1);
        __syncthreads();
        if (threadIdx.x == 0) *flag = (s_any == 0) ? 1 : 0;
    }
}

// x -> tf32-rounded copy
__global__ void k_prepx(const float4* __restrict__ x, float4* __restrict__ xt) {
    long long i = (long long)blockIdx.x * blockDim.x + threadIdx.x;
    if (i >= (long long)NN * INC / 4) return;
    float4 v = __ldg(&x[i]);
    xt[i] = make_float4(ftf(v.x), ftf(v.y), ftf(v.z), ftf(v.w));
}

// build tf32 concatenated weights: wcat1[k][j] (k-stack), wcat2[k][j] (j-concat)
__global__ void k_prepW(const float* __restrict__ ws1, const float* __restrict__ wn1,
                        const float* __restrict__ ws2, const float* __restrict__ wn2,
                        float* __restrict__ wcat1, float* __restrict__ wcat2) {
    int idx = blockIdx.x * blockDim.x + threadIdx.x;
    if (idx >= 2 * HIDC * HIDC) return;
    int m = idx >> 14;             // 0 -> wcat1, 1 -> wcat2
    int rem = idx & 16383;
    int k = rem >> 7, j = rem & 127;
    float v;
    if (m == 0) v = (k < 64) ? ws1[k * HIDC + j] : wn1[(k - 64) * HIDC + j];
    else        v = (j < 64) ? ws2[k * OUTC + j] : wn2[k * OUTC + (j - 64)];
    (m == 0 ? wcat1 : wcat2)[rem] = ftf(v);
}

// ---------------- CSR build kernels ------------------------------------------

__global__ void k_convert(const void* __restrict__ ei, int nE,
                          int* __restrict__ degi, const int* __restrict__ flag) {
    int e = blockIdx.x * blockDim.x + threadIdx.x;
    if (e >= nE) return;
    int d = (*flag) ? (int)((const long long*)ei)[(long long)nE + e]
                    : ((const int*)ei)[nE + e];
    if ((unsigned)d >= NN) d = 0;
    atomicAdd(&degi[d], 1);
}

__global__ __launch_bounds__(1024) void k_scanA(const int* __restrict__ degi,
                                                int* __restrict__ chunksum) {
    __shared__ int s[1024];
    int i = blockIdx.x * 1024 + threadIdx.x;
    s[threadIdx.x] = (i < NN) ? degi[i] : 0;
    __syncthreads();
    for (int off = 512; off > 0; off >>= 1) {
        if (threadIdx.x < off) s[threadIdx.x] += s[threadIdx.x + off];
        __syncthreads();
    }
    if (threadIdx.x == 0) chunksum[blockIdx.x] = s[0];
}

__global__ void k_scanB(const int* __restrict__ chunksum, int* __restrict__ chunkoff) {
    __shared__ int s[128];
    int v = (threadIdx.x < NCHUNK) ? chunksum[threadIdx.x] : 0;
    s[threadIdx.x] = v;
    __syncthreads();
    for (int off = 1; off < 128; off <<= 1) {
        int t = (threadIdx.x >= off) ? s[threadIdx.x - off] : 0;
        __syncthreads();
        s[threadIdx.x] += t;
        __syncthreads();
    }
    if (threadIdx.x < NCHUNK) chunkoff[threadIdx.x] = s[threadIdx.x] - v;
}

__global__ __launch_bounds__(1024) void k_scanC(const int* __restrict__ degi,
                                                const int* __restrict__ chunkoff,
                                                int* __restrict__ rowstart,
                                                int* __restrict__ cursor,
                                                float* __restrict__ dinv) {
    __shared__ int s[1024];
    int i = blockIdx.x * 1024 + threadIdx.x;
    int v = (i < NN) ? degi[i] : 0;
    s[threadIdx.x] = v;
    __syncthreads();
    for (int off = 1; off < 1024; off <<= 1) {
        int t = (threadIdx.x >= off) ? s[threadIdx.x - off] : 0;
        __syncthreads();
        s[threadIdx.x] += t;
        __syncthreads();
    }
    if (i < NN) {
        int excl = s[threadIdx.x] - v + chunkoff[blockIdx.x];
        rowstart[i] = excl;
        cursor[i] = excl;
        dinv[i] = 1.0f / fmaxf((float)v, 1.0f);
    }
}

__global__ void k_scatter(const void* __restrict__ ei, int nE,
                          int* __restrict__ cursor, int* __restrict__ srclist,
                          const int* __restrict__ flag) {
    int e = blockIdx.x * blockDim.x + threadIdx.x;
    if (e >= nE) return;
    int s, d;
    if (*flag) {
        s = (int)((const long long*)ei)[e];
        d = (int)((const long long*)ei)[(long long)nE + e];
    } else {
        s = ((const int*)ei)[e];
        d = ((const int*)ei)[nE + e];
    }
    if ((unsigned)s >= NN) s = 0;
    if ((unsigned)d >= NN) d = 0;
    int p = atomicAdd(&cursor[d], 1);
    srclist[p] = s;
}

// ---------------- gather kernels ---------------------------------------------

// out[node] = tf32_round((sum feat[src]) * dinv[node])   (feeds gemm1 only)
__global__ __launch_bounds__(256) void k_gather1(
    const float4* __restrict__ feat, const int* __restrict__ rowstart,
    const int* __restrict__ degi, const int* __restrict__ srclist,
    const float* __restrict__ dinv, float4* __restrict__ out) {
    int node = blockIdx.x * 8 + (threadIdx.x >> 5);
    if (node >= NN) return;
    int lane = threadIdx.x & 31;
    int half = lane >> 4;
    int c = lane & 15;
    int beg = rowstart[node];
    int cnt = degi[node];
    float4 acc = make_float4(0.f, 0.f, 0.f, 0.f);
    float4 acc2 = make_float4(0.f, 0.f, 0.f, 0.f);
    int i = half;
    for (; i + 2 < cnt; i += 4) {
        int s0 = __ldg(&srclist[beg + i]);
        int s1 = __ldg(&srclist[beg + i + 2]);
        float4 v0 = __ldg(&feat[(long long)s0 * 16 + c]);
        float4 v1 = __ldg(&feat[(long long)s1 * 16 + c]);
        acc.x += v0.x; acc.y += v0.y; acc.z += v0.z; acc.w += v0.w;
        acc2.x += v1.x; acc2.y += v1.y; acc2.z += v1.z; acc2.w += v1.w;
    }
    for (; i < cnt; i += 2) {
        int s = __ldg(&srclist[beg + i]);
        float4 v = __ldg(&feat[(long long)s * 16 + c]);
        acc.x += v.x; acc.y += v.y; acc.z += v.z; acc.w += v.w;
    }
    acc.x += acc2.x; acc.y += acc2.y; acc.z += acc2.z; acc.w += acc2.w;
    acc.x += __shfl_xor_sync(0xffffffffu, acc.x, 16);
    acc.y += __shfl_xor_sync(0xffffffffu, acc.y, 16);
    acc.z += __shfl_xor_sync(0xffffffffu, acc.z, 16);
    acc.w += __shfl_xor_sync(0xffffffffu, acc.w, 16);
    if (half == 0) {
        float di = dinv[node];
        out[(long long)node * 16 + c] =
            make_float4(ftf(acc.x * di), ftf(acc.y * di), ftf(acc.z * di), ftf(acc.w * di));
    }
}

// gather over p (= sp cols 64..127) + epilogue: h2 = relu(s2 + agg*dinv + b2)
__global__ __launch_bounds__(256) void k_gather2(
    const float4* __restrict__ sp, const int* __restrict__ rowstart,
    const int* __restrict__ degi, const int* __restrict__ srclist,
    const float* __restrict__ dinv,
    const float4* __restrict__ b2, float4* __restrict__ h2) {
    int node = blockIdx.x * 8 + (threadIdx.x >> 5);
    if (node >= NN) return;
    int lane = threadIdx.x & 31;
    int half = lane >> 4;
    int c = lane & 15;
    int beg = rowstart[node];
    int cnt = degi[node];
    float4 acc = make_float4(0.f, 0.f, 0.f, 0.f);
    float4 acc2 = make_float4(0.f, 0.f, 0.f, 0.f);
    int i = half;
    for (; i + 2 < cnt; i += 4) {
        int s0 = __ldg(&srclist[beg + i]);
        int s1 = __ldg(&srclist[beg + i + 2]);
        float4 v0 = __ldg(&sp[(long long)s0 * 32 + 16 + c]);
        float4 v1 = __ldg(&sp[(long long)s1 * 32 + 16 + c]);
        acc.x += v0.x; acc.y += v0.y; acc.z += v0.z; acc.w += v0.w;
        acc2.x += v1.x; acc2.y += v1.y; acc2.z += v1.z; acc2.w += v1.w;
    }
    for (; i < cnt; i += 2) {
        int s = __ldg(&srclist[beg + i]);
        float4 v = __ldg(&sp[(long long)s * 32 + 16 + c]);
        acc.x += v.x; acc.y += v.y; acc.z += v.z; acc.w += v.w;
    }
    acc.x += acc2.x; acc.y += acc2.y; acc.z += acc2.z; acc.w += acc2.w;
    acc.x += __shfl_xor_sync(0xffffffffu, acc.x, 16);
    acc.y += __shfl_xor_sync(0xffffffffu, acc.y, 16);
    acc.z += __shfl_xor_sync(0xffffffffu, acc.z, 16);
    acc.w += __shfl_xor_sync(0xffffffffu, acc.w, 16);
    if (half == 0) {
        float di = dinv[node];
        float4 sv = __ldg(&sp[(long long)node * 32 + c]);
        float4 bv = __ldg(&b2[c]);
        float4 r;
        r.x = fmaxf(sv.x + acc.x * di + bv.x, 0.f);
        r.y = fmaxf(sv.y + acc.y * di + bv.y, 0.f);
        r.z = fmaxf(sv.z + acc.z * di + bv.z, 0.f);
        r.w = fmaxf(sv.w + acc.w * di + bv.w, 0.f);
        h2[(long long)node * 16 + c] = r;
    }
}

// ---------------- cp.async double-buffered tf32 GEMM -------------------------
// C[M x 128] = A[M x 128] @ Wcat[128 x 128]; A k-split across A0/A1.
// MODE 0: relu(+bias) + tf32-round store (h1). MODE 1: plain fp32 store (sp).
#define SA_S 36
#define SW_S 136
#define TILE_A_WORDS (128 * SA_S)
#define TILE_W_WORDS (32 * SW_S)
#define BUF_WORDS (TILE_A_WORDS + TILE_W_WORDS)
#define GEMM_SMEM_BYTES (2 * BUF_WORDS * 4)

__device__ __forceinline__ void gemm_load_tiles(
    unsigned* bufA, unsigned* bufW, int kp, int n0,
    const float* A0, int lda0, const float* A1, int lda1,
    const float* Wcat, int tid) {
    const float* Asrc = (kp < 2) ? A0 : A1;
    int lda = (kp < 2) ? lda0 : lda1;
    int colbase = (kp & 1) * 32;
#pragma unroll
    for (int t = 0; t < 4; t++) {
        int idx = tid + t * 256;
        int row = idx >> 3, c4 = idx & 7;
        int grow = n0 + row; if (grow >= NN) grow = NN - 1;
        cp16(&bufA[row * SA_S + c4 * 4], &Asrc[(long long)grow * lda + colbase + c4 * 4]);
    }
#pragma unroll
    for (int t = 0; t < 4; t++) {
        int idx = tid + t * 256;
        int kk = idx >> 5, c4 = idx & 31;
        cp16(&bufW[kk * SW_S + c4 * 4], &Wcat[(long long)(kp * 32 + kk) * 128 + c4 * 4]);
    }
}

template<int MODE>
__global__ __launch_bounds__(256) void k_gemm(
    const float* __restrict__ A0, int lda0,
    const float* __restrict__ A1, int lda1,
    const float* __restrict__ Wcat,
    const float* __restrict__ bias, float* __restrict__ out) {
    extern __shared__ unsigned smem[];
    unsigned* bA[2] = { smem, smem + BUF_WORDS };
    unsigned* bW[2] = { smem + TILE_A_WORDS, smem + BUF_WORDS + TILE_A_WORDS };
    const int tid = threadIdx.x;
    const int lane = tid & 31;
    const int wrp = tid >> 5;
    const int gid = lane >> 2;
    const int tig = lane & 3;
    const int wm = wrp * 16;
    const int n0 = blockIdx.x * 128;

    float4 acc[16];
#pragma unroll
    for (int t = 0; t < 16; t++) acc[t] = make_float4(0.f, 0.f, 0.f, 0.f);

    gemm_load_tiles(bA[0], bW[0], 0, n0, A0, lda0, A1, lda1, Wcat, tid);
    cp_commit();

#pragma unroll
    for (int kp = 0; kp < 4; kp++) {
        if (kp < 3) {
            gemm_load_tiles(bA[(kp + 1) & 1], bW[(kp + 1) & 1], kp + 1, n0,
                            A0, lda0, A1, lda1, Wcat, tid);
            cp_commit();
            cp_wait1();
        } else {
            cp_wait0();
        }
        __syncthreads();
        unsigned* sA = bA[kp & 1];
        unsigned* sW = bW[kp & 1];
#pragma unroll
        for (int ks = 0; ks < 4; ks++) {
            unsigned a0 = sA[(wm + gid) * SA_S + ks * 8 + tig];
            unsigned a1 = sA[(wm + gid + 8) * SA_S + ks * 8 + tig];
            unsigned a2 = sA[(wm + gid) * SA_S + ks * 8 + tig + 4];
            unsigned a3 = sA[(wm + gid + 8) * SA_S + ks * 8 + tig + 4];
#pragma unroll
            for (int nt = 0; nt < 16; nt++) {
                unsigned b0 = sW[(ks * 8 + tig) * SW_S + nt * 8 + gid];
                unsigned b1 = sW[(ks * 8 + tig + 4) * SW_S + nt * 8 + gid];
                mma_tf32(acc[nt], a0, a1, a2, a3, b0, b1);
            }
        }
        __syncthreads();
    }

    int row0 = n0 + wm + gid;
    int row1 = row0 + 8;
#pragma unroll
    for (int nt = 0; nt < 16; nt++) {
        int col = nt * 8 + 2 * tig;
        float2 lo = make_float2(acc[nt].x, acc[nt].y);
        float2 hi = make_float2(acc[nt].z, acc[nt].w);
        if (MODE == 0) {
            float2 bb = __ldg((const float2*)&bias[col]);
            lo.x = ftf(fmaxf(lo.x + bb.x, 0.f)); lo.y = ftf(fmaxf(lo.y + bb.y, 0.f));
            hi.x = ftf(fmaxf(hi.x + bb.x, 0.f)); hi.y = ftf(fmaxf(hi.y + bb.y, 0.f));
        }
        if (row0 < NN) *(float2*)&out[(long long)row0 * 128 + col] = lo;
        if (row1 < NN) *(float2*)&out[(long long)row1 * 128 + col] = hi;
    }
}

// classifier: out = h2 @ wc + bc
__global__ __launch_bounds__(256) void k_out(const float* __restrict__ h2,
                                             const float* __restrict__ wc,
                                             const float* __restrict__ bc,
                                             float* __restrict__ out) {
    __shared__ float sW[OUTC * NCLS];
    __shared__ float sB[NCLS];
    __shared__ float sH[12 * 65];
    const int tid = threadIdx.x;
    const int n0 = blockIdx.x * 12;
    const int nmax = min(12, NN - n0);
    for (int i = tid; i < OUTC * NCLS; i += 256) sW[i] = wc[i];
    if (tid < NCLS) sB[tid] = bc[tid];
    for (int i = tid; i < nmax * OUTC; i += 256) {
        int ln = i >> 6, k = i & 63;
        sH[ln * 65 + k] = h2[(long long)(n0 + ln) * OUTC + k];
    }
    __syncthreads();
    if (tid < 240) {
        int ln = tid / 20, c = tid % 20;
        if (ln < nmax) {
            float acc = sB[c];
#pragma unroll
            for (int k = 0; k < OUTC; k++)
                acc = fmaf(sH[ln * 65 + k], sW[k * NCLS + c], acc);
            out[(long long)(n0 + ln) * NCLS + c] = acc;
        }
    }
}

// ---------------- launch ----------------------------------------------------
extern "C" void kernel_launch(void* const* d_in, const int* in_sizes, int n_in,
                              void* d_out, int out_size) {
    const float* x   = (const float*)d_in[0];
    const void*  ei  = d_in[1];
    const float* ws1 = (const float*)d_in[2];
    const float* wn1 = (const float*)d_in[3];
    const float* b1  = (const float*)d_in[4];
    const float* ws2 = (const float*)d_in[5];
    const float* wn2 = (const float*)d_in[6];
    const float* b2  = (const float*)d_in[7];
    const float* wc  = (const float*)d_in[8];
    const float* bc  = (const float*)d_in[9];
    float* out = (float*)d_out;

    int nE = in_sizes[1] / 2;
    if (nE > NE_MAX) nE = NE_MAX;

    void *p_flag, *p_degi, *p_rs, *p_cur, *p_src, *p_cs, *p_co;
    void *p_dinv, *p_xt, *p_agg1, *p_h1, *p_sp, *p_h2, *p_w1, *p_w2;
    cudaGetSymbolAddress(&p_flag, g_is64);
    cudaGetSymbolAddress(&p_degi, g_degi);
    cudaGetSymbolAddress(&p_rs,   g_rowstart);
    cudaGetSymbolAddress(&p_cur,  g_cursor);
    cudaGetSymbolAddress(&p_src,  g_srclist);
    cudaGetSymbolAddress(&p_cs,   g_chunksum);
    cudaGetSymbolAddress(&p_co,   g_chunkoff);
    cudaGetSymbolAddress(&p_dinv, g_dinv);
    cudaGetSymbolAddress(&p_xt,   g_xt);
    cudaGetSymbolAddress(&p_agg1, g_agg1);
    cudaGetSymbolAddress(&p_h1,   g_h1);
    cudaGetSymbolAddress(&p_sp,   g_sp);
    cudaGetSymbolAddress(&p_h2,   g_h2);
    cudaGetSymbolAddress(&p_w1,   g_wcat1);
    cudaGetSymbolAddress(&p_w2,   g_wcat2);
    int*   flag  = (int*)p_flag;
    int*   degi  = (int*)p_degi;
    int*   rs    = (int*)p_rs;
    int*   cur   = (int*)p_cur;
    int*   src   = (int*)p_src;
    int*   cs    = (int*)p_cs;
    int*   co    = (int*)p_co;
    float* dinv  = (float*)p_dinv;
    float* xt    = (float*)p_xt;
    float* agg1  = (float*)p_agg1;
    float* h1    = (float*)p_h1;
    float* sp    = (float*)p_sp;
    float* h2    = (float*)p_h2;
    float* wcat1 = (float*)p_w1;
    float* wcat2 = (float*)p_w2;

    cudaFuncSetAttribute(k_gemm<0>, cudaFuncAttributeMaxDynamicSharedMemorySize,
                         GEMM_SMEM_BYTES);
    cudaFuncSetAttribute(k_gemm<1>, cudaFuncAttributeMaxDynamicSharedMemorySize,
                         GEMM_SMEM_BYTES);

    // init + prep
    k_init<<<(NN + 255) / 256, 256>>>((const int*)ei, in_sizes[1], flag, degi);
    k_prepx<<<(NN * INC / 4 + 255) / 256, 256>>>((const float4*)x, (float4*)xt);
    k_prepW<<<(2 * HIDC * HIDC + 255) / 256, 256>>>(ws1, wn1, ws2, wn2, wcat1, wcat2);

    // CSR build
    k_convert<<<(nE + 255) / 256, 256>>>(ei, nE, degi, flag);
    k_scanA<<<NCHUNK, 1024>>>(degi, cs);
    k_scanB<<<1, 128>>>(cs, co);
    k_scanC<<<NCHUNK, 1024>>>(degi, co, rs, cur, dinv);
    k_scatter<<<(nE + 255) / 256, 256>>>(ei, nE, cur, src, flag);

    const int gemm_blocks = (NN + 127) / 128;

    // layer 1
    k_gather1<<<(NN + 7) / 8, 256>>>((const float4*)x, rs, degi, src, dinv,
                                     (float4*)agg1);
    k_gemm<0><<<gemm_blocks, 256, GEMM_SMEM_BYTES>>>(xt, INC, agg1, INC, wcat1, b1, h1);

    // layer 2
    k_gemm<1><<<gemm_blocks, 256, GEMM_SMEM_BYTES>>>(h1, HIDC, h1 + 64, HIDC, wcat2,
                                                     nullptr, sp);
    k_gather2<<<(NN + 7) / 8, 256>>>((const float4*)sp, rs, degi, src, dinv,
                                     (const float4*)b2, (float4*)h2);

    // classifier
    k_out<<<(NN + 11) / 12, 256>>>(h2, wc, bc, out);
}

// round 13
// speedup vs baseline: 2.4099x; 1.0299x over previous
#include <cuda_runtime.h>
#include <cuda_bf16.h>

#define NN 100000
#define NE_MAX 1600000
#define INC 64
#define HIDC 128
#define OUTC 64
#define NCLS 20
#define NCHUNK 98          // ceil(NN/1024)

// ---------------- device scratch (static globals; no allocation) ------------
__device__ int   g_is64;
__device__ int   g_cnt;
__device__ int   g_degi[NN];
__device__ int   g_rowstart[NN];
__device__ int   g_cursor[NN];
__device__ int   g_srclist[NE_MAX];
__device__ float g_dinv[NN];
__device__ __align__(16) float g_xt[(size_t)NN * INC];     // tf32-rounded x
__device__ __align__(16) float g_agg1[(size_t)NN * INC];   // tf32-rounded agg*dinv
__device__ __align__(16) float g_h1[(size_t)NN * HIDC];    // tf32-rounded h1
__device__ __align__(16) float g_sp[(size_t)NN * HIDC];    // [s2 | p] fp32
__device__ __align__(16) float g_wcat1[HIDC * HIDC];       // tf32 [Ws1;Wn1]
__device__ __align__(16) float g_wcat2[HIDC * HIDC];       // tf32 [Ws2|Wn2]

// ---------------- helpers ----------------------------------------------------

__device__ __forceinline__ unsigned f2tf32(float f) {
    unsigned r; asm("cvt.rna.tf32.f32 %0, %1;" : "=r"(r) : "f"(f)); return r;
}
__device__ __forceinline__ float ftf(float f) { return __uint_as_float(f2tf32(f)); }

__device__ __forceinline__ void mma_tf32(float4& d,
                                         unsigned a0, unsigned a1, unsigned a2, unsigned a3,
                                         unsigned b0, unsigned b1) {
    asm("mma.sync.aligned.m16n8k8.row.col.f32.tf32.tf32.f32 "
        "{%0,%1,%2,%3}, {%4,%5,%6,%7}, {%8,%9}, {%0,%1,%2,%3};"
        : "+f"(d.x), "+f"(d.y), "+f"(d.z), "+f"(d.w)
        : "r"(a0), "r"(a1), "r"(a2), "r"(a3), "r"(b0), "r"(b1));
}

__device__ __forceinline__ void cp16(void* smem, const void* g) {
    unsigned s = (unsigned)__cvta_generic_to_shared(smem);
    asm volatile("cp.async.cg.shared.global [%0], [%1], 16;" :: "r"(s), "l"(g));
}
__device__ __forceinline__ void cp_commit() { asm volatile("cp.async.commit_group;"); }
__device__ __forceinline__ void cp_wait1()  { asm volatile("cp.async.wait_group 1;" ::: "memory"); }
__device__ __forceinline__ void cp_wait0()  { asm volatile("cp.async.wait_group 0;" ::: "memory"); }

// ---------------- init / prep kernels ----------------------------------------

__global__ void k_init(const int* __restrict__ ei32, int n32,
                       int* __restrict__ flag, int* __restrict__ degi,
                       int* __restrict__ cnt) {
    int i = blockIdx.x * blockDim.x + threadIdx.x;
    if (i < NN) degi[i] = 0;
    if (i == 0) *cnt = 0;
    if (blockIdx.x == 0) {
        __shared__ int s_any;
        if (threadIdx.x == 0) s_any = 0;
        __syncthreads();
        int nonzero = 0;
        int limit = n32 < 16384 ? n32 : 16384;
        for (int k = 1 + 2 * threadIdx.x; k < limit; k += 2 * blockDim.x)
            if (ei32[k] != 0) nonzero = 1;
        if (nonzero) atomicOr(&s_any, 1);
        __syncthreads();
        if (threadIdx.x == 0) *flag = (s_any == 0) ? 1 : 0;
    }
}

__global__ void k_prepx(const float4* __restrict__ x, float4* __restrict__ xt) {
    long long i = (long long)blockIdx.x * blockDim.x + threadIdx.x;
    if (i >= (long long)NN * INC / 4) return;
    float4 v = __ldg(&x[i]);
    xt[i] = make_float4(ftf(v.x), ftf(v.y), ftf(v.z), ftf(v.w));
}

__global__ void k_prepW(const float* __restrict__ ws1, const float* __restrict__ wn1,
                        const float* __restrict__ ws2, const float* __restrict__ wn2,
                        float* __restrict__ wcat1, float* __restrict__ wcat2) {
    int idx = blockIdx.x * blockDim.x + threadIdx.x;
    if (idx >= 2 * HIDC * HIDC) return;
    int m = idx >> 14;
    int rem = idx & 16383;
    int k = rem >> 7, j = rem & 127;
    float v;
    if (m == 0) v = (k < 64) ? ws1[k * HIDC + j] : wn1[(k - 64) * HIDC + j];
    else        v = (j < 64) ? ws2[k * OUTC + j] : wn2[k * OUTC + (j - 64)];
    (m == 0 ? wcat1 : wcat2)[rem] = ftf(v);
}

// ---------------- CSR build kernels ------------------------------------------

__global__ void k_convert(const void* __restrict__ ei, int nE,
                          int* __restrict__ degi, const int* __restrict__ flag) {
    int e = blockIdx.x * blockDim.x + threadIdx.x;
    if (e >= nE) return;
    int d = (*flag) ? (int)((const long long*)ei)[(long long)nE + e]
                    : ((const int*)ei)[nE + e];
    if ((unsigned)d >= NN) d = 0;
    atomicAdd(&degi[d], 1);
}

// single-pass offsets: block inclusive scan + atomic global base
__global__ __launch_bounds__(1024) void k_offsets(const int* __restrict__ degi,
                                                  int* __restrict__ rowstart,
                                                  int* __restrict__ cursor,
                                                  float* __restrict__ dinv,
                                                  int* __restrict__ cnt) {
    __shared__ int s[1024];
    __shared__ int sbase;
    int tid = threadIdx.x;
    int i = blockIdx.x * 1024 + tid;
    int v = (i < NN) ? degi[i] : 0;
    s[tid] = v;
    __syncthreads();
    for (int off = 1; off < 1024; off <<= 1) {
        int t = (tid >= off) ? s[tid - off] : 0;
        __syncthreads();
        s[tid] += t;
        __syncthreads();
    }
    if (tid == 1023) sbase = atomicAdd(cnt, s[1023]);
    __syncthreads();
    if (i < NN) {
        int excl = sbase + s[tid] - v;
        rowstart[i] = excl;
        cursor[i] = excl;
        dinv[i] = 1.0f / fmaxf((float)v, 1.0f);
    }
}

__global__ void k_scatter(const void* __restrict__ ei, int nE,
                          int* __restrict__ cursor, int* __restrict__ srclist,
                          const int* __restrict__ flag) {
    int e = blockIdx.x * blockDim.x + threadIdx.x;
    if (e >= nE) return;
    int s, d;
    if (*flag) {
        s = (int)((const long long*)ei)[e];
        d = (int)((const long long*)ei)[(long long)nE + e];
    } else {
        s = ((const int*)ei)[e];
        d = ((const int*)ei)[nE + e];
    }
    if ((unsigned)s >= NN) s = 0;
    if ((unsigned)d >= NN) d = 0;
    int p = atomicAdd(&cursor[d], 1);
    srclist[p] = s;
}

// ---------------- gather kernels ---------------------------------------------

__global__ __launch_bounds__(256) void k_gather1(
    const float4* __restrict__ feat, const int* __restrict__ rowstart,
    const int* __restrict__ degi, const int* __restrict__ srclist,
    const float* __restrict__ dinv, float4* __restrict__ out) {
    int node = blockIdx.x * 8 + (threadIdx.x >> 5);
    if (node >= NN) return;
    int lane = threadIdx.x & 31;
    int half = lane >> 4;
    int c = lane & 15;
    int beg = rowstart[node];
    int cnt = degi[node];
    float4 acc = make_float4(0.f, 0.f, 0.f, 0.f);
    float4 acc2 = make_float4(0.f, 0.f, 0.f, 0.f);
    int i = half;
    for (; i + 2 < cnt; i += 4) {
        int s0 = __ldg(&srclist[beg + i]);
        int s1 = __ldg(&srclist[beg + i + 2]);
        float4 v0 = __ldg(&feat[(long long)s0 * 16 + c]);
        float4 v1 = __ldg(&feat[(long long)s1 * 16 + c]);
        acc.x += v0.x; acc.y += v0.y; acc.z += v0.z; acc.w += v0.w;
        acc2.x += v1.x; acc2.y += v1.y; acc2.z += v1.z; acc2.w += v1.w;
    }
    for (; i < cnt; i += 2) {
        int s = __ldg(&srclist[beg + i]);
        float4 v = __ldg(&feat[(long long)s * 16 + c]);
        acc.x += v.x; acc.y += v.y; acc.z += v.z; acc.w += v.w;
    }
    acc.x += acc2.x; acc.y += acc2.y; acc.z += acc2.z; acc.w += acc2.w;
    acc.x += __shfl_xor_sync(0xffffffffu, acc.x, 16);
    acc.y += __shfl_xor_sync(0xffffffffu, acc.y, 16);
    acc.z += __shfl_xor_sync(0xffffffffu, acc.z, 16);
    acc.w += __shfl_xor_sync(0xffffffffu, acc.w, 16);
    if (half == 0) {
        float di = dinv[node];
        out[(long long)node * 16 + c] =
            make_float4(ftf(acc.x * di), ftf(acc.y * di), ftf(acc.z * di), ftf(acc.w * di));
    }
}

// gather over p + layer2 epilogue + FUSED classifier:
// h2 = relu(s2 + agg*dinv + b2); out[node] = h2 @ wc + bc   (h2 never stored)
__global__ __launch_bounds__(256) void k_gather2(
    const float4* __restrict__ sp, const int* __restrict__ rowstart,
    const int* __restrict__ degi, const int* __restrict__ srclist,
    const float* __restrict__ dinv, const float4* __restrict__ b2,
    const float* __restrict__ wc, const float* __restrict__ bc,
    float* __restrict__ out) {
    __shared__ float sWcT[NCLS * 64];   // transposed: [cls][k], 5 KB
    __shared__ float sBc[NCLS];
    const int tid = threadIdx.x;
    for (int i = tid; i < NCLS * 64; i += 256) {
        int cls = i >> 6, k = i & 63;
        sWcT[i] = wc[k * NCLS + cls];
    }
    if (tid < NCLS) sBc[tid] = bc[tid];
    __syncthreads();

    int node = blockIdx.x * 8 + (tid >> 5);
    if (node >= NN) return;
    int lane = tid & 31;
    int half = lane >> 4;
    int c = lane & 15;
    int beg = rowstart[node];
    int cnt = degi[node];
    float4 acc = make_float4(0.f, 0.f, 0.f, 0.f);
    float4 acc2 = make_float4(0.f, 0.f, 0.f, 0.f);
    int i = half;
    for (; i + 2 < cnt; i += 4) {
        int s0 = __ldg(&srclist[beg + i]);
        int s1 = __ldg(&srclist[beg + i + 2]);
        float4 v0 = __ldg(&sp[(long long)s0 * 32 + 16 + c]);
        float4 v1 = __ldg(&sp[(long long)s1 * 32 + 16 + c]);
        acc.x += v0.x; acc.y += v0.y; acc.z += v0.z; acc.w += v0.w;
        acc2.x += v1.x; acc2.y += v1.y; acc2.z += v1.z; acc2.w += v1.w;
    }
    for (; i < cnt; i += 2) {
        int s = __ldg(&srclist[beg + i]);
        float4 v = __ldg(&sp[(long long)s * 32 + 16 + c]);
        acc.x += v.x; acc.y += v.y; acc.z += v.z; acc.w += v.w;
    }
    acc.x += acc2.x; acc.y += acc2.y; acc.z += acc2.z; acc.w += acc2.w;
    acc.x += __shfl_xor_sync(0xffffffffu, acc.x, 16);
    acc.y += __shfl_xor_sync(0xffffffffu, acc.y, 16);
    acc.z += __shfl_xor_sync(0xffffffffu, acc.z, 16);
    acc.w += __shfl_xor_sync(0xffffffffu, acc.w, 16);

    // h2 values for columns 4c..4c+3, computed in ALL lanes
    float di = dinv[node];
    float4 sv = __ldg(&sp[(long long)node * 32 + c]);
    float4 bv = __ldg(&b2[c]);
    float4 r;
    r.x = fmaxf(sv.x + acc.x * di + bv.x, 0.f);
    r.y = fmaxf(sv.y + acc.y * di + bv.y, 0.f);
    r.z = fmaxf(sv.z + acc.z * di + bv.z, 0.f);
    r.w = fmaxf(sv.w + acc.w * di + bv.w, 0.f);

    // classifier: half 0 -> classes 0..9, half 1 -> classes 10..19
    const int clsbase = half * 10;
    float part[10];
#pragma unroll
    for (int t = 0; t < 10; t++) {
        float4 w = *(const float4*)&sWcT[(clsbase + t) * 64 + 4 * c];
        part[t] = r.x * w.x + r.y * w.y + r.z * w.z + r.w * w.w;
    }
#pragma unroll
    for (int m = 1; m <= 8; m <<= 1)
#pragma unroll
        for (int t = 0; t < 10; t++)
            part[t] += __shfl_xor_sync(0xffffffffu, part[t], m);
    if (c == 0) {
#pragma unroll
        for (int t = 0; t < 10; t++)
            out[(long long)node * NCLS + clsbase + t] = part[t] + sBc[clsbase + t];
    }
}

// ---------------- cp.async double-buffered tf32 GEMM -------------------------
#define SA_S 36
#define SW_S 136
#define TILE_A_WORDS (128 * SA_S)
#define TILE_W_WORDS (32 * SW_S)
#define BUF_WORDS (TILE_A_WORDS + TILE_W_WORDS)
#define GEMM_SMEM_BYTES (2 * BUF_WORDS * 4)

__device__ __forceinline__ void gemm_load_tiles(
    unsigned* bufA, unsigned* bufW, int kp, int n0,
    const float* A0, int lda0, const float* A1, int lda1,
    const float* Wcat, int tid) {
    const float* Asrc = (kp < 2) ? A0 : A1;
    int lda = (kp < 2) ? lda0 : lda1;
    int colbase = (kp & 1) * 32;
#pragma unroll
    for (int t = 0; t < 4; t++) {
        int idx = tid + t * 256;
        int row = idx >> 3, c4 = idx & 7;
        int grow = n0 + row; if (grow >= NN) grow = NN - 1;
        cp16(&bufA[row * SA_S + c4 * 4], &Asrc[(long long)grow * lda + colbase + c4 * 4]);
    }
#pragma unroll
    for (int t = 0; t < 4; t++) {
        int idx = tid + t * 256;
        int kk = idx >> 5, c4 = idx & 31;
        cp16(&bufW[kk * SW_S + c4 * 4], &Wcat[(long long)(kp * 32 + kk) * 128 + c4 * 4]);
    }
}

template<int MODE>
__global__ __launch_bounds__(256) void k_gemm(
    const float* __restrict__ A0, int lda0,
    const float* __restrict__ A1, int lda1,
    const float* __restrict__ Wcat,
    const float* __restrict__ bias, float* __restrict__ out) {
    extern __shared__ unsigned smem[];
    unsigned* bA[2] = { smem, smem + BUF_WORDS };
    unsigned* bW[2] = { smem + TILE_A_WORDS, smem + BUF_WORDS + TILE_A_WORDS };
    const int tid = threadIdx.x;
    const int lane = tid & 31;
    const int wrp = tid >> 5;
    const int gid = lane >> 2;
    const int tig = lane & 3;
    const int wm = wrp * 16;
    const int n0 = blockIdx.x * 128;

    float4 acc[16];
#pragma unroll
    for (int t = 0; t < 16; t++) acc[t] = make_float4(0.f, 0.f, 0.f, 0.f);

    gemm_load_tiles(bA[0], bW[0], 0, n0, A0, lda0, A1, lda1, Wcat, tid);
    cp_commit();

#pragma unroll
    for (int kp = 0; kp < 4; kp++) {
        if (kp < 3) {
            gemm_load_tiles(bA[(kp + 1) & 1], bW[(kp + 1) & 1], kp + 1, n0,
                            A0, lda0, A1, lda1, Wcat, tid);
            cp_commit();
            cp_wait1();
        } else {
            cp_wait0();
        }
        __syncthreads();
        unsigned* sA = bA[kp & 1];
        unsigned* sW = bW[kp & 1];
#pragma unroll
        for (int ks = 0; ks < 4; ks++) {
            unsigned a0 = sA[(wm + gid) * SA_S + ks * 8 + tig];
            unsigned a1 = sA[(wm + gid + 8) * SA_S + ks * 8 + tig];
            unsigned a2 = sA[(wm + gid) * SA_S + ks * 8 + tig + 4];
            unsigned a3 = sA[(wm + gid + 8) * SA_S + ks * 8 + tig + 4];
#pragma unroll
            for (int nt = 0; nt < 16; nt++) {
                unsigned b0 = sW[(ks * 8 + tig) * SW_S + nt * 8 + gid];
                unsigned b1 = sW[(ks * 8 + tig + 4) * SW_S + nt * 8 + gid];
                mma_tf32(acc[nt], a0, a1, a2, a3, b0, b1);
            }
        }
        __syncthreads();
    }

    int row0 = n0 + wm + gid;
    int row1 = row0 + 8;
#pragma unroll
    for (int nt = 0; nt < 16; nt++) {
        int col = nt * 8 + 2 * tig;
        float2 lo = make_float2(acc[nt].x, acc[nt].y);
        float2 hi = make_float2(acc[nt].z, acc[nt].w);
        if (MODE == 0) {
            float2 bb = __ldg((const float2*)&bias[col]);
            lo.x = ftf(fmaxf(lo.x + bb.x, 0.f)); lo.y = ftf(fmaxf(lo.y + bb.y, 0.f));
            hi.x = ftf(fmaxf(hi.x + bb.x, 0.f)); hi.y = ftf(fmaxf(hi.y + bb.y, 0.f));
        }
        if (row0 < NN) *(float2*)&out[(long long)row0 * 128 + col] = lo;
        if (row1 < NN) *(float2*)&out[(long long)row1 * 128 + col] = hi;
    }
}

// ---------------- launch ----------------------------------------------------
extern "C" void kernel_launch(void* const* d_in, const int* in_sizes, int n_in,
                              void* d_out, int out_size) {
    const float* x   = (const float*)d_in[0];
    const void*  ei  = d_in[1];
    const float* ws1 = (const float*)d_in[2];
    const float* wn1 = (const float*)d_in[3];
    const float* b1  = (const float*)d_in[4];
    const float* ws2 = (const float*)d_in[5];
    const float* wn2 = (const float*)d_in[6];
    const float* b2  = (const float*)d_in[7];
    const float* wc  = (const float*)d_in[8];
    const float* bc  = (const float*)d_in[9];
    float* out = (float*)d_out;

    int nE = in_sizes[1] / 2;
    if (nE > NE_MAX) nE = NE_MAX;

    void *p_flag, *p_cnt, *p_degi, *p_rs, *p_cur, *p_src;
    void *p_dinv, *p_xt, *p_agg1, *p_h1, *p_sp, *p_w1, *p_w2;
    cudaGetSymbolAddress(&p_flag, g_is64);
    cudaGetSymbolAddress(&p_cnt,  g_cnt);
    cudaGetSymbolAddress(&p_degi, g_degi);
    cudaGetSymbolAddress(&p_rs,   g_rowstart);
    cudaGetSymbolAddress(&p_cur,  g_cursor);
    cudaGetSymbolAddress(&p_src,  g_srclist);
    cudaGetSymbolAddress(&p_dinv, g_dinv);
    cudaGetSymbolAddress(&p_xt,   g_xt);
    cudaGetSymbolAddress(&p_agg1, g_agg1);
    cudaGetSymbolAddress(&p_h1,   g_h1);
    cudaGetSymbolAddress(&p_sp,   g_sp);
    cudaGetSymbolAddress(&p_w1,   g_wcat1);
    cudaGetSymbolAddress(&p_w2,   g_wcat2);
    int*   flag  = (int*)p_flag;
    int*   cnt   = (int*)p_cnt;
    int*   degi  = (int*)p_degi;
    int*   rs    = (int*)p_rs;
    int*   cur   = (int*)p_cur;
    int*   src   = (int*)p_src;
    float* dinv  = (float*)p_dinv;
    float* xt    = (float*)p_xt;
    float* agg1  = (float*)p_agg1;
    float* h1    = (float*)p_h1;
    float* sp    = (float*)p_sp;
    float* wcat1 = (float*)p_w1;
    float* wcat2 = (float*)p_w2;

    cudaFuncSetAttribute(k_gemm<0>, cudaFuncAttributeMaxDynamicSharedMemorySize,
                         GEMM_SMEM_BYTES);
    cudaFuncSetAttribute(k_gemm<1>, cudaFuncAttributeMaxDynamicSharedMemorySize,
                         GEMM_SMEM_BYTES);

    // init + prep
    k_init<<<(NN + 255) / 256, 256>>>((const int*)ei, in_sizes[1], flag, degi, cnt);
    k_prepx<<<(NN * INC / 4 + 255) / 256, 256>>>((const float4*)x, (float4*)xt);
    k_prepW<<<(2 * HIDC * HIDC + 255) / 256, 256>>>(ws1, wn1, ws2, wn2, wcat1, wcat2);

    // CSR build
    k_convert<<<(nE + 255) / 256, 256>>>(ei, nE, degi, flag);
    k_offsets<<<NCHUNK, 1024>>>(degi, rs, cur, dinv, cnt);
    k_scatter<<<(nE + 255) / 256, 256>>>(ei, nE, cur, src, flag);

    const int gemm_blocks = (NN + 127) / 128;

    // layer 1
    k_gather1<<<(NN + 7) / 8, 256>>>((const float4*)x, rs, degi, src, dinv,
                                     (float4*)agg1);
    k_gemm<0><<<gemm_blocks, 256, GEMM_SMEM_BYTES>>>(xt, INC, agg1, INC, wcat1, b1, h1);

    // layer 2 + fused classifier
    k_gemm<1><<<gemm_blocks, 256, GEMM_SMEM_BYTES>>>(h1, HIDC, h1 + 64, HIDC, wcat2,
                                                     nullptr, sp);
    k_gather2<<<(NN + 7) / 8, 256>>>((const float4*)sp, rs, degi, src, dinv,
                                     (const float4*)b2, wc, bc, out);
}

// round 14
// speedup vs baseline: 2.4877x; 1.0323x over previous
#include <cuda_runtime.h>
#include <cuda_bf16.h>

#define NN 100000
#define NE_MAX 1600000
#define INC 64
#define HIDC 128
#define OUTC 64
#define NCLS 20
#define NCHUNK 98          // ceil(NN/1024)

// ---------------- device scratch (static globals; no allocation) ------------
__device__ int   g_is64;
__device__ int   g_cnt;
__device__ int   g_degi[NN];
__device__ int   g_rowstart[NN];
__device__ int   g_cursor[NN];
__device__ int   g_srclist[NE_MAX];
__device__ float g_dinv[NN];
__device__ __align__(16) float g_xt[(size_t)NN * INC];     // tf32-rounded x
__device__ __align__(16) float g_agg1[(size_t)NN * INC];   // tf32-rounded agg*dinv
__device__ __align__(16) float g_sp[(size_t)NN * HIDC];    // [s2 | p] fp32
__device__ __align__(16) float g_wcat1[HIDC * HIDC];       // tf32 [Ws1;Wn1]
__device__ __align__(16) float g_wcat2[HIDC * HIDC];       // tf32 [Ws2|Wn2]

// ---------------- helpers ----------------------------------------------------

__device__ __forceinline__ unsigned f2tf32(float f) {
    unsigned r; asm("cvt.rna.tf32.f32 %0, %1;" : "=r"(r) : "f"(f)); return r;
}
__device__ __forceinline__ float ftf(float f) { return __uint_as_float(f2tf32(f)); }

__device__ __forceinline__ void mma_tf32(float4& d,
                                         unsigned a0, unsigned a1, unsigned a2, unsigned a3,
                                         unsigned b0, unsigned b1) {
    asm("mma.sync.aligned.m16n8k8.row.col.f32.tf32.tf32.f32 "
        "{%0,%1,%2,%3}, {%4,%5,%6,%7}, {%8,%9}, {%0,%1,%2,%3};"
        : "+f"(d.x), "+f"(d.y), "+f"(d.z), "+f"(d.w)
        : "r"(a0), "r"(a1), "r"(a2), "r"(a3), "r"(b0), "r"(b1));
}

__device__ __forceinline__ void cp16(void* smem, const void* g) {
    unsigned s = (unsigned)__cvta_generic_to_shared(smem);
    asm volatile("cp.async.cg.shared.global [%0], [%1], 16;" :: "r"(s), "l"(g));
}
__device__ __forceinline__ void cp_commit() { asm volatile("cp.async.commit_group;"); }
__device__ __forceinline__ void cp_wait1()  { asm volatile("cp.async.wait_group 1;" ::: "memory"); }
__device__ __forceinline__ void cp_wait0()  { asm volatile("cp.async.wait_group 0;" ::: "memory"); }

// ---------------- init / prep kernels ----------------------------------------

__global__ void k_init(const int* __restrict__ ei32, int n32,
                       int* __restrict__ flag, int* __restrict__ degi,
                       int* __restrict__ cnt) {
    int i = blockIdx.x * blockDim.x + threadIdx.x;
    if (i < NN) degi[i] = 0;
    if (i == 0) *cnt = 0;
    if (blockIdx.x == 0) {
        __shared__ int s_any;
        if (threadIdx.x == 0) s_any = 0;
        __syncthreads();
        int nonzero = 0;
        int limit = n32 < 16384 ? n32 : 16384;
        for (int k = 1 + 2 * threadIdx.x; k < limit; k += 2 * blockDim.x)
            if (ei32[k] != 0) nonzero = 1;
        if (nonzero) atomicOr(&s_any, 1);
        __syncthreads();
        if (threadIdx.x == 0) *flag = (s_any == 0) ? 1 : 0;
    }
}

__global__ void k_prepx(const float4* __restrict__ x, float4* __restrict__ xt) {
    long long i = (long long)blockIdx.x * blockDim.x + threadIdx.x;
    if (i >= (long long)NN * INC / 4) return;
    float4 v = __ldg(&x[i]);
    xt[i] = make_float4(ftf(v.x), ftf(v.y), ftf(v.z), ftf(v.w));
}

__global__ void k_prepW(const float* __restrict__ ws1, const float* __restrict__ wn1,
                        const float* __restrict__ ws2, const float* __restrict__ wn2,
                        float* __restrict__ wcat1, float* __restrict__ wcat2) {
    int idx = blockIdx.x * blockDim.x + threadIdx.x;
    if (idx >= 2 * HIDC * HIDC) return;
    int m = idx >> 14;
    int rem = idx & 16383;
    int k = rem >> 7, j = rem & 127;
    float v;
    if (m == 0) v = (k < 64) ? ws1[k * HIDC + j] : wn1[(k - 64) * HIDC + j];
    else        v = (j < 64) ? ws2[k * OUTC + j] : wn2[k * OUTC + (j - 64)];
    (m == 0 ? wcat1 : wcat2)[rem] = ftf(v);
}

// ---------------- CSR build kernels ------------------------------------------

__global__ void k_convert(const void* __restrict__ ei, int nE,
                          int* __restrict__ degi, const int* __restrict__ flag) {
    int e = blockIdx.x * blockDim.x + threadIdx.x;
    if (e >= nE) return;
    int d = (*flag) ? (int)((const long long*)ei)[(long long)nE + e]
                    : ((const int*)ei)[nE + e];
    if ((unsigned)d >= NN) d = 0;
    atomicAdd(&degi[d], 1);
}

// single-pass offsets: block inclusive scan + atomic global base
__global__ __launch_bounds__(1024) void k_offsets(const int* __restrict__ degi,
                                                  int* __restrict__ rowstart,
                                                  int* __restrict__ cursor,
                                                  float* __restrict__ dinv,
                                                  int* __restrict__ cnt) {
    __shared__ int s[1024];
    __shared__ int sbase;
    int tid = threadIdx.x;
    int i = blockIdx.x * 1024 + tid;
    int v = (i < NN) ? degi[i] : 0;
    s[tid] = v;
    __syncthreads();
    for (int off = 1; off < 1024; off <<= 1) {
        int t = (tid >= off) ? s[tid - off] : 0;
        __syncthreads();
        s[tid] += t;
        __syncthreads();
    }
    if (tid == 1023) sbase = atomicAdd(cnt, s[1023]);
    __syncthreads();
    if (i < NN) {
        int excl = sbase + s[tid] - v;
        rowstart[i] = excl;
        cursor[i] = excl;
        dinv[i] = 1.0f / fmaxf((float)v, 1.0f);
    }
}

__global__ void k_scatter(const void* __restrict__ ei, int nE,
                          int* __restrict__ cursor, int* __restrict__ srclist,
                          const int* __restrict__ flag) {
    int e = blockIdx.x * blockDim.x + threadIdx.x;
    if (e >= nE) return;
    int s, d;
    if (*flag) {
        s = (int)((const long long*)ei)[e];
        d = (int)((const long long*)ei)[(long long)nE + e];
    } else {
        s = ((const int*)ei)[e];
        d = ((const int*)ei)[nE + e];
    }
    if ((unsigned)s >= NN) s = 0;
    if ((unsigned)d >= NN) d = 0;
    int p = atomicAdd(&cursor[d], 1);
    srclist[p] = s;
}

// ---------------- gather kernels ---------------------------------------------

__global__ __launch_bounds__(256) void k_gather1(
    const float4* __restrict__ feat, const int* __restrict__ rowstart,
    const int* __restrict__ degi, const int* __restrict__ srclist,
    const float* __restrict__ dinv, float4* __restrict__ out) {
    int node = blockIdx.x * 8 + (threadIdx.x >> 5);
    if (node >= NN) return;
    int lane = threadIdx.x & 31;
    int half = lane >> 4;
    int c = lane & 15;
    int beg = rowstart[node];
    int cnt = degi[node];
    float4 acc = make_float4(0.f, 0.f, 0.f, 0.f);
    float4 acc2 = make_float4(0.f, 0.f, 0.f, 0.f);
    int i = half;
    for (; i + 2 < cnt; i += 4) {
        int s0 = __ldg(&srclist[beg + i]);
        int s1 = __ldg(&srclist[beg + i + 2]);
        float4 v0 = __ldg(&feat[(long long)s0 * 16 + c]);
        float4 v1 = __ldg(&feat[(long long)s1 * 16 + c]);
        acc.x += v0.x; acc.y += v0.y; acc.z += v0.z; acc.w += v0.w;
        acc2.x += v1.x; acc2.y += v1.y; acc2.z += v1.z; acc2.w += v1.w;
    }
    for (; i < cnt; i += 2) {
        int s = __ldg(&srclist[beg + i]);
        float4 v = __ldg(&feat[(long long)s * 16 + c]);
        acc.x += v.x; acc.y += v.y; acc.z += v.z; acc.w += v.w;
    }
    acc.x += acc2.x; acc.y += acc2.y; acc.z += acc2.z; acc.w += acc2.w;
    acc.x += __shfl_xor_sync(0xffffffffu, acc.x, 16);
    acc.y += __shfl_xor_sync(0xffffffffu, acc.y, 16);
    acc.z += __shfl_xor_sync(0xffffffffu, acc.z, 16);
    acc.w += __shfl_xor_sync(0xffffffffu, acc.w, 16);
    if (half == 0) {
        float di = dinv[node];
        out[(long long)node * 16 + c] =
            make_float4(ftf(acc.x * di), ftf(acc.y * di), ftf(acc.z * di), ftf(acc.w * di));
    }
}

// gather over p + layer2 epilogue + fused classifier
__global__ __launch_bounds__(256) void k_gather2(
    const float4* __restrict__ sp, const int* __restrict__ rowstart,
    const int* __restrict__ degi, const int* __restrict__ srclist,
    const float* __restrict__ dinv, const float4* __restrict__ b2,
    const float* __restrict__ wc, const float* __restrict__ bc,
    float* __restrict__ out) {
    __shared__ float sWcT[NCLS * 64];   // transposed: [cls][k], 5 KB
    __shared__ float sBc[NCLS];
    const int tid = threadIdx.x;
    for (int i = tid; i < NCLS * 64; i += 256) {
        int cls = i >> 6, k = i & 63;
        sWcT[i] = wc[k * NCLS + cls];
    }
    if (tid < NCLS) sBc[tid] = bc[tid];
    __syncthreads();

    int node = blockIdx.x * 8 + (tid >> 5);
    if (node >= NN) return;
    int lane = tid & 31;
    int half = lane >> 4;
    int c = lane & 15;
    int beg = rowstart[node];
    int cnt = degi[node];
    float4 acc = make_float4(0.f, 0.f, 0.f, 0.f);
    float4 acc2 = make_float4(0.f, 0.f, 0.f, 0.f);
    int i = half;
    for (; i + 2 < cnt; i += 4) {
        int s0 = __ldg(&srclist[beg + i]);
        int s1 = __ldg(&srclist[beg + i + 2]);
        float4 v0 = __ldg(&sp[(long long)s0 * 32 + 16 + c]);
        float4 v1 = __ldg(&sp[(long long)s1 * 32 + 16 + c]);
        acc.x += v0.x; acc.y += v0.y; acc.z += v0.z; acc.w += v0.w;
        acc2.x += v1.x; acc2.y += v1.y; acc2.z += v1.z; acc2.w += v1.w;
    }
    for (; i < cnt; i += 2) {
        int s = __ldg(&srclist[beg + i]);
        float4 v = __ldg(&sp[(long long)s * 32 + 16 + c]);
        acc.x += v.x; acc.y += v.y; acc.z += v.z; acc.w += v.w;
    }
    acc.x += acc2.x; acc.y += acc2.y; acc.z += acc2.z; acc.w += acc2.w;
    acc.x += __shfl_xor_sync(0xffffffffu, acc.x, 16);
    acc.y += __shfl_xor_sync(0xffffffffu, acc.y, 16);
    acc.z += __shfl_xor_sync(0xffffffffu, acc.z, 16);
    acc.w += __shfl_xor_sync(0xffffffffu, acc.w, 16);

    float di = dinv[node];
    float4 sv = __ldg(&sp[(long long)node * 32 + c]);
    float4 bv = __ldg(&b2[c]);
    float4 r;
    r.x = fmaxf(sv.x + acc.x * di + bv.x, 0.f);
    r.y = fmaxf(sv.y + acc.y * di + bv.y, 0.f);
    r.z = fmaxf(sv.z + acc.z * di + bv.z, 0.f);
    r.w = fmaxf(sv.w + acc.w * di + bv.w, 0.f);

    const int clsbase = half * 10;
    float part[10];
#pragma unroll
    for (int t = 0; t < 10; t++) {
        float4 w = *(const float4*)&sWcT[(clsbase + t) * 64 + 4 * c];
        part[t] = r.x * w.x + r.y * w.y + r.z * w.z + r.w * w.w;
    }
#pragma unroll
    for (int m = 1; m <= 8; m <<= 1)
#pragma unroll
        for (int t = 0; t < 10; t++)
            part[t] += __shfl_xor_sync(0xffffffffu, part[t], m);
    if (c == 0) {
#pragma unroll
        for (int t = 0; t < 10; t++)
            out[(long long)node * NCLS + clsbase + t] = part[t] + sBc[clsbase + t];
    }
}

// ---------------- FUSED double-GEMM ------------------------------------------
// Stage 1: h1_tile = relu(xt@Wcat1[0:64] + agg1@Wcat1[64:128] + b1)  (tf32, smem)
// Stage 2: sp_tile = h1_tile @ Wcat2    -> global (h1 never touches gmem)
#define SA_S 36
#define SW_S 136
#define TILE_A_WORDS (128 * SA_S)
#define TILE_W_WORDS (32 * SW_S)
#define BUF_WORDS (TILE_A_WORDS + TILE_W_WORDS)
#define H1T_S 132
#define H1T_WORDS (128 * H1T_S)
#define FUSED_SMEM_WORDS (H1T_WORDS + 2 * TILE_W_WORDS)  // 25600 (>= 2*BUF_WORDS)
#define FUSED_SMEM_BYTES (FUSED_SMEM_WORDS * 4)          // 100 KB

__device__ __forceinline__ void load_tiles1(
    unsigned* bufA, unsigned* bufW, int kp, int n0,
    const float* xt, const float* agg1, const float* Wcat1, int tid) {
    const float* Asrc = (kp < 2) ? xt : agg1;
    int colbase = (kp & 1) * 32;
#pragma unroll
    for (int t = 0; t < 4; t++) {
        int idx = tid + t * 256;
        int row = idx >> 3, c4 = idx & 7;
        int grow = n0 + row; if (grow >= NN) grow = NN - 1;
        cp16(&bufA[row * SA_S + c4 * 4], &Asrc[(long long)grow * INC + colbase + c4 * 4]);
    }
#pragma unroll
    for (int t = 0; t < 4; t++) {
        int idx = tid + t * 256;
        int kk = idx >> 5, c4 = idx & 31;
        cp16(&bufW[kk * SW_S + c4 * 4], &Wcat1[(long long)(kp * 32 + kk) * 128 + c4 * 4]);
    }
}

__device__ __forceinline__ void load_w2(unsigned* bufW, int kp, const float* Wcat2, int tid) {
#pragma unroll
    for (int t = 0; t < 4; t++) {
        int idx = tid + t * 256;
        int kk = idx >> 5, c4 = idx & 31;
        cp16(&bufW[kk * SW_S + c4 * 4], &Wcat2[(long long)(kp * 32 + kk) * 128 + c4 * 4]);
    }
}

__global__ __launch_bounds__(256) void k_gemm_fused(
    const float* __restrict__ xt, const float* __restrict__ agg1,
    const float* __restrict__ Wcat1, const float* __restrict__ Wcat2,
    const float* __restrict__ bias, float* __restrict__ sp) {
    extern __shared__ unsigned smem[];
    unsigned* bA[2] = { smem, smem + BUF_WORDS };
    unsigned* bW[2] = { smem + TILE_A_WORDS, smem + BUF_WORDS + TILE_A_WORDS };
    unsigned* h1t = smem;                                  // aliases stage-1 bufs
    unsigned* w2b[2] = { smem + H1T_WORDS, smem + H1T_WORDS + TILE_W_WORDS };
    const int tid = threadIdx.x;
    const int lane = tid & 31;
    const int wrp = tid >> 5;
    const int gid = lane >> 2;
    const int tig = lane & 3;
    const int wm = wrp * 16;
    const int n0 = blockIdx.x * 128;

    float4 acc[16];
#pragma unroll
    for (int t = 0; t < 16; t++) acc[t] = make_float4(0.f, 0.f, 0.f, 0.f);

    // ---- stage 1 ----
    load_tiles1(bA[0], bW[0], 0, n0, xt, agg1, Wcat1, tid);
    cp_commit();
#pragma unroll
    for (int kp = 0; kp < 4; kp++) {
        if (kp < 3) {
            load_tiles1(bA[(kp + 1) & 1], bW[(kp + 1) & 1], kp + 1, n0, xt, agg1, Wcat1, tid);
            cp_commit();
            cp_wait1();
        } else {
            cp_wait0();
        }
        __syncthreads();
        unsigned* sA = bA[kp & 1];
        unsigned* sW = bW[kp & 1];
#pragma unroll
        for (int ks = 0; ks < 4; ks++) {
            unsigned a0 = sA[(wm + gid) * SA_S + ks * 8 + tig];
            unsigned a1 = sA[(wm + gid + 8) * SA_S + ks * 8 + tig];
            unsigned a2 = sA[(wm + gid) * SA_S + ks * 8 + tig + 4];
            unsigned a3 = sA[(wm + gid + 8) * SA_S + ks * 8 + tig + 4];
#pragma unroll
            for (int nt = 0; nt < 16; nt++) {
                unsigned b0 = sW[(ks * 8 + tig) * SW_S + nt * 8 + gid];
                unsigned b1 = sW[(ks * 8 + tig + 4) * SW_S + nt * 8 + gid];
                mma_tf32(acc[nt], a0, a1, a2, a3, b0, b1);
            }
        }
        __syncthreads();
    }

    // ---- transition: issue first w2 slice, write h1 tile to smem ----
    load_w2(w2b[0], 0, Wcat2, tid);
    cp_commit();
#pragma unroll
    for (int nt = 0; nt < 16; nt++) {
        int col = nt * 8 + 2 * tig;
        float2 bb = __ldg((const float2*)&bias[col]);
        unsigned* r0p = &h1t[(wm + gid) * H1T_S + col];
        unsigned* r1p = &h1t[(wm + gid + 8) * H1T_S + col];
        r0p[0] = f2tf32(fmaxf(acc[nt].x + bb.x, 0.f));
        r0p[1] = f2tf32(fmaxf(acc[nt].y + bb.y, 0.f));
        r1p[0] = f2tf32(fmaxf(acc[nt].z + bb.x, 0.f));
        r1p[1] = f2tf32(fmaxf(acc[nt].w + bb.y, 0.f));
    }
#pragma unroll
    for (int t = 0; t < 16; t++) acc[t] = make_float4(0.f, 0.f, 0.f, 0.f);
    __syncthreads();

    // ---- stage 2 ----
#pragma unroll
    for (int kp = 0; kp < 4; kp++) {
        if (kp < 3) {
            load_w2(w2b[(kp + 1) & 1], kp + 1, Wcat2, tid);
            cp_commit();
            cp_wait1();
        } else {
            cp_wait0();
        }
        __syncthreads();
        unsigned* sW = w2b[kp & 1];
#pragma unroll
        for (int ks = 0; ks < 4; ks++) {
            unsigned a0 = h1t[(wm + gid) * H1T_S + kp * 32 + ks * 8 + tig];
            unsigned a1 = h1t[(wm + gid + 8) * H1T_S + kp * 32 + ks * 8 + tig];
            unsigned a2 = h1t[(wm + gid) * H1T_S + kp * 32 + ks * 8 + tig + 4];
            unsigned a3 = h1t[(wm + gid + 8) * H1T_S + kp * 32 + ks * 8 + tig + 4];
#pragma unroll
            for (int nt = 0; nt < 16; nt++) {
                unsigned b0 = sW[(ks * 8 + tig) * SW_S + nt * 8 + gid];
                unsigned b1 = sW[(ks * 8 + tig + 4) * SW_S + nt * 8 + gid];
                mma_tf32(acc[nt], a0, a1, a2, a3, b0, b1);
            }
        }
        __syncthreads();
    }

    int row0 = n0 + wm + gid;
    int row1 = row0 + 8;
#pragma unroll
    for (int nt = 0; nt < 16; nt++) {
        int col = nt * 8 + 2 * tig;
        if (row0 < NN)
            *(float2*)&sp[(long long)row0 * 128 + col] = make_float2(acc[nt].x, acc[nt].y);
        if (row1 < NN)
            *(float2*)&sp[(long long)row1 * 128 + col] = make_float2(acc[nt].z, acc[nt].w);
    }
}

// ---------------- launch ----------------------------------------------------
extern "C" void kernel_launch(void* const* d_in, const int* in_sizes, int n_in,
                              void* d_out, int out_size) {
    const float* x   = (const float*)d_in[0];
    const void*  ei  = d_in[1];
    const float* ws1 = (const float*)d_in[2];
    const float* wn1 = (const float*)d_in[3];
    const float* b1  = (const float*)d_in[4];
    const float* ws2 = (const float*)d_in[5];
    const float* wn2 = (const float*)d_in[6];
    const float* b2  = (const float*)d_in[7];
    const float* wc  = (const float*)d_in[8];
    const float* bc  = (const float*)d_in[9];
    float* out = (float*)d_out;

    int nE = in_sizes[1] / 2;
    if (nE > NE_MAX) nE = NE_MAX;

    void *p_flag, *p_cnt, *p_degi, *p_rs, *p_cur, *p_src;
    void *p_dinv, *p_xt, *p_agg1, *p_sp, *p_w1, *p_w2;
    cudaGetSymbolAddress(&p_flag, g_is64);
    cudaGetSymbolAddress(&p_cnt,  g_cnt);
    cudaGetSymbolAddress(&p_degi, g_degi);
    cudaGetSymbolAddress(&p_rs,   g_rowstart);
    cudaGetSymbolAddress(&p_cur,  g_cursor);
    cudaGetSymbolAddress(&p_src,  g_srclist);
    cudaGetSymbolAddress(&p_dinv, g_dinv);
    cudaGetSymbolAddress(&p_xt,   g_xt);
    cudaGetSymbolAddress(&p_agg1, g_agg1);
    cudaGetSymbolAddress(&p_sp,   g_sp);
    cudaGetSymbolAddress(&p_w1,   g_wcat1);
    cudaGetSymbolAddress(&p_w2,   g_wcat2);
    int*   flag  = (int*)p_flag;
    int*   cnt   = (int*)p_cnt;
    int*   degi  = (int*)p_degi;
    int*   rs    = (int*)p_rs;
    int*   cur   = (int*)p_cur;
    int*   src   = (int*)p_src;
    float* dinv  = (float*)p_dinv;
    float* xt    = (float*)p_xt;
    float* agg1  = (float*)p_agg1;
    float* sp    = (float*)p_sp;
    float* wcat1 = (float*)p_w1;
    float* wcat2 = (float*)p_w2;

    cudaFuncSetAttribute(k_gemm_fused, cudaFuncAttributeMaxDynamicSharedMemorySize,
                         FUSED_SMEM_BYTES);

    // init + prep
    k_init<<<(NN + 255) / 256, 256>>>((const int*)ei, in_sizes[1], flag, degi, cnt);
    k_prepx<<<(NN * INC / 4 + 255) / 256, 256>>>((const float4*)x, (float4*)xt);
    k_prepW<<<(2 * HIDC * HIDC + 255) / 256, 256>>>(ws1, wn1, ws2, wn2, wcat1, wcat2);

    // CSR build
    k_convert<<<(nE + 255) / 256, 256>>>(ei, nE, degi, flag);
    k_offsets<<<NCHUNK, 1024>>>(degi, rs, cur, dinv, cnt);
    k_scatter<<<(nE + 255) / 256, 256>>>(ei, nE, cur, src, flag);

    // layer 1 gather
    k_gather1<<<(NN + 7) / 8, 256>>>((const float4*)x, rs, degi, src, dinv,
                                     (float4*)agg1);

    // fused layer1+layer2 GEMM
    k_gemm_fused<<<(NN + 127) / 128, 256, FUSED_SMEM_BYTES>>>(xt, agg1, wcat1, wcat2,
                                                              b1, sp);

    // layer 2 gather + epilogue + classifier
    k_gather2<<<(NN + 7) / 8, 256>>>((const float4*)sp, rs, degi, src, dinv,
                                     (const float4*)b2, wc, bc, out);
}